// round 9
// baseline (speedup 1.0000x reference)
#include <cuda_runtime.h>
#include <math.h>
#include <cstdint>

#define FRAMES 256
#define PATCHES 64
#define DIMX 512
#define HEADS 8
#define DH 64
#define DFF 1024
#define KPROJ 128
#define NT 257              // temporal seq len (cls + 256 frames)
#define NS 65               // spatial seq len (cls + 64 patches)
#define MT (PATCHES * NT)   // 16448 rows temporal
#define MS (FRAMES * NS)    // 16640 rows spatial

// ---------------- scratch (device globals; no allocation allowed) ----------
__device__ float g_QKV1[MT * 3 * DIMX];
__device__ float g_O1[MT * DIMX];
__device__ float g_Y1[MT * DIMX];
__device__ float g_QKV2[MS * 3 * DIMX];
__device__ float g_O2[MS * DIMX];
__device__ float g_Y2[MS * DIMX];
__device__ float g_H[MS * DFF];
// transposed weights (filled every call by transpose_w)
__device__ float g_WqkvTt[3 * DIMX * DIMX];
__device__ float g_WoTt[DIMX * DIMX];
__device__ float g_WqkvTs[3 * DIMX * DIMX];
__device__ float g_WoTs[DIMX * DIMX];
__device__ float g_W1T[DFF * DIMX];
__device__ float g_W2T[DIMX * DFF];

// ---------------- weight transpose: WT[n][k] = W[k][n] ----------------------
__global__ void transpose_w(const float* __restrict__ W, float* __restrict__ WT,
                            int K, int N) {
    __shared__ float t[32][33];
    int k0 = blockIdx.y * 32, n0 = blockIdx.x * 32;
    int tx = threadIdx.x & 31, ty = threadIdx.x >> 5;
#pragma unroll
    for (int i = 0; i < 32; i += 8)
        t[ty + i][tx] = W[(size_t)(k0 + ty + i) * N + n0 + tx];
    __syncthreads();
#pragma unroll
    for (int i = 0; i < 32; i += 8)
        WT[(size_t)(n0 + ty + i) * K + k0 + tx] = t[tx][ty + i];
}

// ---------------- row remaps (gathers folded into GEMM loads) ---------------
template <int RM>
__device__ __forceinline__ const float* arow(const float* base, int r) {
    if (RM == 1) {
        int t = r % NT, pb = r / NT;
        int src = (t == 0) ? 0 : (1 + (t - 1) * PATCHES + pb);
        return base + (size_t)src * DIMX;
    } else {
        int s = r % NS, fb = r / NS;
        int srow = (s == 0) ? ((fb & 63) * NT) : ((s - 1) * NT + 1 + fb);
        return base + (size_t)srow * DIMX;
    }
}

// ---------------- shared helpers ---------------------------------------------
__device__ __forceinline__ void cp_async16(uint32_t dst, const float* src, int srcsize) {
    asm volatile("cp.async.cg.shared.global [%0], [%1], 16, %2;\n"
                 :: "r"(dst), "l"(src), "r"(srcsize));
}
__device__ __forceinline__ void ldsm4(uint32_t (&r)[4], uint32_t addr) {
    asm volatile("ldmatrix.sync.aligned.m8n8.x4.shared.b16 {%0,%1,%2,%3}, [%4];"
                 : "=r"(r[0]), "=r"(r[1]), "=r"(r[2]), "=r"(r[3]) : "r"(addr));
}
__device__ __forceinline__ void mma8u(float (&c)[4], const uint32_t (&a)[4],
                                      uint32_t b0, uint32_t b1) {
    asm volatile(
        "mma.sync.aligned.m16n8k8.row.col.f32.tf32.tf32.f32 "
        "{%0,%1,%2,%3}, {%4,%5,%6,%7}, {%8,%9}, {%0,%1,%2,%3};"
        : "+f"(c[0]), "+f"(c[1]), "+f"(c[2]), "+f"(c[3])
        : "r"(a[0]), "r"(a[1]), "r"(a[2]), "r"(a[3]), "r"(b0), "r"(b1));
}
__device__ __forceinline__ void mma8f(float (&c)[4], const float (&a)[4],
                                      uint32_t b0, uint32_t b1) {
    asm volatile(
        "mma.sync.aligned.m16n8k8.row.col.f32.tf32.tf32.f32 "
        "{%0,%1,%2,%3}, {%4,%5,%6,%7}, {%8,%9}, {%0,%1,%2,%3};"
        : "+f"(c[0]), "+f"(c[1]), "+f"(c[2]), "+f"(c[3])
        : "r"(__float_as_uint(a[0])), "r"(__float_as_uint(a[1])),
          "r"(__float_as_uint(a[2])), "r"(__float_as_uint(a[3])),
          "r"(b0), "r"(b1));
}

// ---------------- tf32 GEMM, B pre-transposed, all-ldmatrix operands --------
// C[M,N] = A[M,K] @ B[K,N] with BT[N,K] in gmem. 128x128x32 tiles, 8 warps.
#define ASTR 36
#define BTSTR 36
#define A_TILE (128 * ASTR)
#define B_TILE (128 * BTSTR)
#define GEMM_SMEM ((2 * A_TILE + 2 * B_TILE) * 4)

template <int EPI, int RMA, int RMR>
__global__ void __launch_bounds__(256, 2)
tf32_gemm(const float* __restrict__ A, const float* __restrict__ BT,
          float* __restrict__ C, const float* __restrict__ bias,
          const float* __restrict__ R, int M, int N, int K) {
    extern __shared__ float smem[];
    float* As = smem;                    // [2][128][ASTR]
    float* Bs = smem + 2 * A_TILE;       // [2][128 n][BTSTR]
    uint32_t sA = (uint32_t)__cvta_generic_to_shared(As);
    uint32_t sB = (uint32_t)__cvta_generic_to_shared(Bs);

    int tid = threadIdx.x;
    int lane = tid & 31, warp = tid >> 5;
    int wm = warp & 1, wn = warp >> 1;
    int m0 = blockIdx.y * 128;
    int n0 = blockIdx.x * 128;

    int aRow = lane & 15;
    int aCol4 = (lane >> 4) * 4;
    uint32_t aBase[4];
#pragma unroll
    for (int i = 0; i < 4; i++)
        aBase[i] = ((wm * 64 + i * 16 + aRow) * ASTR + aCol4) * 4;
    // B ldmatrix per-lane base: row n (within tile), col k chunk
    uint32_t bBase[4];
#pragma unroll
    for (int j = 0; j < 4; j++)
        bBase[j] = ((wn * 32 + j * 8 + (lane & 7)) * BTSTR + (lane >> 3) * 4) * 4;

    int tig = lane & 3, g = lane >> 2;

    float c[4][4][4];
#pragma unroll
    for (int i = 0; i < 4; i++)
#pragma unroll
        for (int j = 0; j < 4; j++)
#pragma unroll
            for (int r = 0; r < 4; r++) c[i][j][r] = 0.f;

    int ntiles = K >> 5;

    auto issue = [&](int t, int buf) {
        int k0 = t << 5;
#pragma unroll
        for (int it = 0; it < 4; it++) {       // A: 128 rows x 8 chunks
            int idx = tid + it * 256;
            int row = idx >> 3, ch = (idx & 7) * 4;
            int gr = m0 + row;
            int ok = (gr < M) ? 16 : 0;
            int grc = min(gr, M - 1);
            const float* src;
            if (RMA == 0) src = A + (size_t)grc * K + k0 + ch;
            else          src = arow<RMA>(A, grc) + k0 + ch;
            cp_async16(sA + (buf * A_TILE + row * ASTR + ch) * 4, src, ok);
        }
#pragma unroll
        for (int it = 0; it < 4; it++) {       // BT: 128 n-rows x 8 k-chunks
            int idx = tid + it * 256;
            int row = idx >> 3, ch = (idx & 7) * 4;
            cp_async16(sB + (buf * B_TILE + row * BTSTR + ch) * 4,
                       BT + (size_t)(n0 + row) * K + k0 + ch, 16);
        }
        asm volatile("cp.async.commit_group;");
    };

    issue(0, 0);

    for (int t = 0; t < ntiles; t++) {
        int buf = t & 1;
        if (t + 1 < ntiles) {
            issue(t + 1, (t + 1) & 1);
            asm volatile("cp.async.wait_group 1;");
        } else {
            asm volatile("cp.async.wait_group 0;");
        }
        __syncthreads();

        uint32_t sAb = sA + buf * A_TILE * 4;
        uint32_t sBb = sB + buf * B_TILE * 4;
#pragma unroll
        for (int kk2 = 0; kk2 < 32; kk2 += 16) {
            uint32_t bf[4][4];
#pragma unroll
            for (int j = 0; j < 4; j++)
                ldsm4(bf[j], sBb + bBase[j] + kk2 * 4);
#pragma unroll
            for (int h = 0; h < 2; h++) {
                uint32_t a[4][4];
#pragma unroll
                for (int i = 0; i < 4; i++)
                    ldsm4(a[i], sAb + aBase[i] + (kk2 + 8 * h) * 4);
#pragma unroll
                for (int i = 0; i < 4; i++)
#pragma unroll
                    for (int j = 0; j < 4; j++)
                        mma8u(c[i][j], a[i], bf[j][2 * h], bf[j][2 * h + 1]);
            }
        }
        __syncthreads();
    }

    // epilogue
#pragma unroll
    for (int i = 0; i < 4; i++) {
        int r0 = m0 + wm * 64 + i * 16 + g;
#pragma unroll
        for (int j = 0; j < 4; j++) {
            int col = n0 + wn * 32 + j * 8 + 2 * tig;
#pragma unroll
            for (int half = 0; half < 2; half++) {
                int m = r0 + half * 8;
                if (m >= M) continue;
                float v0 = c[i][j][2 * half + 0];
                float v1 = c[i][j][2 * half + 1];
                if (EPI == 1) {
                    const float* Rrow = (RMR == 0) ? R + (size_t)m * N : arow<RMR>(R, m);
                    v0 += Rrow[col];
                    v1 += Rrow[col + 1];
                } else if (EPI == 2) {
                    v0 += bias[col];
                    v1 += bias[col + 1];
                    v0 = 0.5f * v0 * (1.f + erff(v0 * 0.70710678118654752f));
                    v1 = 0.5f * v1 * (1.f + erff(v1 * 0.70710678118654752f));
                } else if (EPI == 3) {
                    const float* Rrow = R + (size_t)m * N;
                    v0 += bias[col] + Rrow[col];
                    v1 += bias[col + 1] + Rrow[col + 1];
                }
                *(float2*)(C + (size_t)m * N + col) = make_float2(v0, v1);
            }
        }
    }
}

// ---------------- tensor-core attention (all-ldmatrix operand feed) ---------
#define KSTR 68     // Ks[key][d]; ldmatrix rows: 17r mod 8 distinct
#define PSTR 68
#define TKPAD 272
#define VTSTR_T 276 // Vt[d][key] temporal: 69 mod 8 = 5 (odd) -> conflict-free
#define VTSTR_S 132 // Vt[d][key] spatial
#define SMEM_AT ((TKPAD * KSTR + DH * VTSTR_T + 8 * 16 * PSTR) * 4)

// One key-block of NTILE*8 keys.
template <int NTILE, int VTS>
__device__ __forceinline__ void attn_kblock(
    uint32_t sKs, uint32_t sVt, float* __restrict__ Pw, uint32_t sPw,
    const float (&qa)[8][4], float (&oc)[8][4],
    float& sum0, float& sum1, int lane, int keybase, int klimit)
{
    int g = lane >> 2, tig = lane & 3;
    int l7 = lane & 7, l8g = (lane >> 3) * 4;

    float sc[NTILE][4];
#pragma unroll
    for (int nt = 0; nt < NTILE; nt++) {
        sc[nt][0] = sc[nt][1] = sc[nt][2] = sc[nt][3] = 0.f;
        uint32_t rowb = sKs + ((keybase + nt * 8 + l7) * KSTR + l8g) * 4;
#pragma unroll
        for (int dp = 0; dp < 4; dp++) {
            uint32_t bb[4];
            ldsm4(bb, rowb + dp * 64);
            mma8f(sc[nt], qa[2 * dp], bb[0], bb[1]);
            mma8f(sc[nt], qa[2 * dp + 1], bb[2], bb[3]);
        }
    }
#pragma unroll
    for (int nt = 0; nt < NTILE; nt++) {
        int key = keybase + nt * 8 + 2 * tig;
        float e0 = (key     < klimit) ? __expf(sc[nt][0]) : 0.f;
        float e1 = (key + 1 < klimit) ? __expf(sc[nt][1]) : 0.f;
        float e2 = (key     < klimit) ? __expf(sc[nt][2]) : 0.f;
        float e3 = (key + 1 < klimit) ? __expf(sc[nt][3]) : 0.f;
        sum0 += e0 + e1;
        sum1 += e2 + e3;
        *(float2*)(Pw + g * PSTR + nt * 8 + 2 * tig)       = make_float2(e0, e1);
        *(float2*)(Pw + (g + 8) * PSTR + nt * 8 + 2 * tig) = make_float2(e2, e3);
    }
    __syncwarp();
    uint32_t pf[NTILE][4];
#pragma unroll
    for (int kc = 0; kc < NTILE; kc++)
        ldsm4(pf[kc], sPw + ((lane & 15) * PSTR + kc * 8 + (lane >> 4) * 4) * 4);
#pragma unroll
    for (int nt = 0; nt < 8; nt++) {
        uint32_t rowb = sVt + ((nt * 8 + l7) * VTS + keybase + l8g) * 4;
#pragma unroll
        for (int kc2 = 0; kc2 < NTILE / 2; kc2++) {
            uint32_t vb[4];
            ldsm4(vb, rowb + kc2 * 64);
            mma8u(oc[nt], pf[2 * kc2], vb[0], vb[1]);
            mma8u(oc[nt], pf[2 * kc2 + 1], vb[2], vb[3]);
        }
    }
    __syncwarp();
}

// ---------------- temporal attention -----------------------------------------
__global__ void __launch_bounds__(256) attn_t_mma() {
    extern __shared__ float sm[];
    float* Ks = sm;                       // [TKPAD][KSTR]
    float* Vt = Ks + TKPAD * KSTR;        // [DH][VTSTR_T]
    float* Ps = Vt + DH * VTSTR_T;
    uint32_t sKs = (uint32_t)__cvta_generic_to_shared(Ks);
    uint32_t sVt = (uint32_t)__cvta_generic_to_shared(Vt);
    uint32_t sPs = (uint32_t)__cvta_generic_to_shared(Ps);

    int b = blockIdx.x >> 3, h = blockIdx.x & 7;
    const float* base = g_QKV1 + (size_t)b * NT * 1536;

    for (int i = threadIdx.x; i < TKPAD * 16; i += 256) {
        int t = i >> 4, c4 = (i & 15) * 4;
        float4 kv = make_float4(0.f, 0.f, 0.f, 0.f);
        float4 vv = make_float4(0.f, 0.f, 0.f, 0.f);
        if (t < NT) {
            kv = *(const float4*)(base + (size_t)t * 1536 + 512 + h * 64 + c4);
            vv = *(const float4*)(base + (size_t)t * 1536 + 1024 + h * 64 + c4);
        }
        *(float4*)(Ks + t * KSTR + c4) = kv;
        Vt[(c4 + 0) * VTSTR_T + t] = vv.x;
        Vt[(c4 + 1) * VTSTR_T + t] = vv.y;
        Vt[(c4 + 2) * VTSTR_T + t] = vv.z;
        Vt[(c4 + 3) * VTSTR_T + t] = vv.w;
    }
    __syncthreads();

    int lane = threadIdx.x & 31, warp = threadIdx.x >> 5;
    int g = lane >> 2, tig = lane & 3;
    float* Pw = Ps + warp * 16 * PSTR;
    uint32_t sPw = sPs + warp * 16 * PSTR * 4;

    for (int qt = warp; qt < 17; qt += 8) {
        int q0 = qt * 16;
        int r0 = min(q0 + g, NT - 1), r1 = min(q0 + g + 8, NT - 1);
        const float* Q0 = base + (size_t)r0 * 1536 + h * 64;
        const float* Q1 = base + (size_t)r1 * 1536 + h * 64;
        float qa[8][4];
#pragma unroll
        for (int kk = 0; kk < 8; kk++) {
            qa[kk][0] = Q0[kk * 8 + tig] * 0.125f;
            qa[kk][1] = Q1[kk * 8 + tig] * 0.125f;
            qa[kk][2] = Q0[kk * 8 + tig + 4] * 0.125f;
            qa[kk][3] = Q1[kk * 8 + tig + 4] * 0.125f;
        }
        float oc[8][4];
#pragma unroll
        for (int nt = 0; nt < 8; nt++)
            oc[nt][0] = oc[nt][1] = oc[nt][2] = oc[nt][3] = 0.f;
        float sum0 = 0.f, sum1 = 0.f;

#pragma unroll
        for (int kb = 0; kb < 4; kb++)
            attn_kblock<8, VTSTR_T>(sKs, sVt, Pw, sPw, qa, oc, sum0, sum1,
                                    lane, kb * 64, NT);
        attn_kblock<2, VTSTR_T>(sKs, sVt, Pw, sPw, qa, oc, sum0, sum1,
                                lane, 256, NT);

        sum0 += __shfl_xor_sync(0xffffffffu, sum0, 1);
        sum0 += __shfl_xor_sync(0xffffffffu, sum0, 2);
        sum1 += __shfl_xor_sync(0xffffffffu, sum1, 1);
        sum1 += __shfl_xor_sync(0xffffffffu, sum1, 2);
        float inv0 = 1.f / sum0, inv1 = 1.f / sum1;

        int row0 = q0 + g, row1 = q0 + g + 8;
        if (row0 < NT) {
            float* op = g_O1 + ((size_t)b * NT + row0) * 512 + h * 64;
#pragma unroll
            for (int nt = 0; nt < 8; nt++)
                *(float2*)(op + nt * 8 + 2 * tig) =
                    make_float2(oc[nt][0] * inv0, oc[nt][1] * inv0);
        }
        if (row1 < NT) {
            float* op = g_O1 + ((size_t)b * NT + row1) * 512 + h * 64;
#pragma unroll
            for (int nt = 0; nt < 8; nt++)
                *(float2*)(op + nt * 8 + 2 * tig) =
                    make_float2(oc[nt][2] * inv1, oc[nt][3] * inv1);
        }
    }
}

// ---------------- fused spatial: E-projection (mma) + attention (mma) --------
#define ETSTR 76
#define KVSTR 72
#define SMEM_SF ((128 * ETSTR + 2 * 72 * KVSTR + KPROJ * KSTR + DH * VTSTR_S + 8 * 16 * PSTR) * 4)

__global__ void __launch_bounds__(256) attn_s_fused(const float* __restrict__ E) {
    extern __shared__ float sm[];
    float* ET   = sm;                        // [128][ETSTR]
    float* Ksrc = ET + 128 * ETSTR;          // [72][KVSTR]
    float* Vsrc = Ksrc + 72 * KVSTR;         // [72][KVSTR]
    float* Ks   = Vsrc + 72 * KVSTR;         // [128][KSTR]  projected KE (key-major)
    float* Vt   = Ks + KPROJ * KSTR;         // [64][VTSTR_S] projected VE transposed
    float* Ps   = Vt + DH * VTSTR_S;
    uint32_t sKs = (uint32_t)__cvta_generic_to_shared(Ks);
    uint32_t sVt = (uint32_t)__cvta_generic_to_shared(Vt);
    uint32_t sPs = (uint32_t)__cvta_generic_to_shared(Ps);

    int blk = blockIdx.x;           // fb*8 + h
    int fb = blk >> 3, h = blk & 7;
    const float* base = g_QKV2 + (size_t)fb * NS * 1536;

    for (int i = threadIdx.x; i < 128 * 11; i += 256) {
        int kk = i / 11, j = 65 + i % 11;
        ET[kk * ETSTR + j] = 0.f;
    }
    for (int i = threadIdx.x; i < 7 * KVSTR; i += 256) {
        Ksrc[65 * KVSTR + i] = 0.f;
        Vsrc[65 * KVSTR + i] = 0.f;
    }
    for (int i = threadIdx.x; i < NS * 128; i += 256) {
        int j = i >> 7, kk = i & 127;
        ET[kk * ETSTR + j] = E[i];
    }
    for (int i = threadIdx.x; i < NS * 16; i += 256) {
        int j = i >> 4, c4 = (i & 15) * 4;
        float4 kv = *(const float4*)(base + (size_t)j * 1536 + 512 + h * 64 + c4);
        float4 vv = *(const float4*)(base + (size_t)j * 1536 + 1024 + h * 64 + c4);
        *(float4*)(Ksrc + j * KVSTR + c4) = kv;
        *(float4*)(Vsrc + j * KVSTR + c4) = vv;
    }
    __syncthreads();

    int lane = threadIdx.x & 31, warp = threadIdx.x >> 5;
    int g = lane >> 2, tig = lane & 3;

    // phase 1: KE = E^T @ K -> Ks[key][d];  VE = E^T @ V -> Vt[d][key]
    {
        int m0w = warp * 16;
        float ck[8][4], cv[8][4];
#pragma unroll
        for (int nf = 0; nf < 8; nf++) {
            ck[nf][0] = ck[nf][1] = ck[nf][2] = ck[nf][3] = 0.f;
            cv[nf][0] = cv[nf][1] = cv[nf][2] = cv[nf][3] = 0.f;
        }
#pragma unroll
        for (int ks = 0; ks < 9; ks++) {
            int j0 = ks * 8;
            float a[4];
            a[0] = ET[(m0w + g) * ETSTR + j0 + tig];
            a[1] = ET[(m0w + g + 8) * ETSTR + j0 + tig];
            a[2] = ET[(m0w + g) * ETSTR + j0 + tig + 4];
            a[3] = ET[(m0w + g + 8) * ETSTR + j0 + tig + 4];
#pragma unroll
            for (int nf = 0; nf < 8; nf++) {
                const float* Kp = Ksrc + (j0 + tig) * KVSTR + nf * 8 + g;
                mma8f(ck[nf], a, __float_as_uint(Kp[0]), __float_as_uint(Kp[4 * KVSTR]));
                const float* Vp = Vsrc + (j0 + tig) * KVSTR + nf * 8 + g;
                mma8f(cv[nf], a, __float_as_uint(Vp[0]), __float_as_uint(Vp[4 * KVSTR]));
            }
        }
#pragma unroll
        for (int nf = 0; nf < 8; nf++) {
            int col = nf * 8 + 2 * tig;
            *(float2*)(Ks + (m0w + g) * KSTR + col)     = make_float2(ck[nf][0], ck[nf][1]);
            *(float2*)(Ks + (m0w + g + 8) * KSTR + col) = make_float2(ck[nf][2], ck[nf][3]);
            Vt[(col + 0) * VTSTR_S + m0w + g]     = cv[nf][0];
            Vt[(col + 1) * VTSTR_S + m0w + g]     = cv[nf][1];
            Vt[(col + 0) * VTSTR_S + m0w + g + 8] = cv[nf][2];
            Vt[(col + 1) * VTSTR_S + m0w + g + 8] = cv[nf][3];
        }
    }
    __syncthreads();

    // phase 2: attention over 128 projected keys
    float* Pw = Ps + warp * 16 * PSTR;
    uint32_t sPw = sPs + warp * 16 * PSTR * 4;
    for (int qt = warp; qt < 5; qt += 8) {
        int q0 = qt * 16;
        int r0 = min(q0 + g, NS - 1), r1 = min(q0 + g + 8, NS - 1);
        const float* Q0 = base + (size_t)r0 * 1536 + h * 64;
        const float* Q1 = base + (size_t)r1 * 1536 + h * 64;
        float qa[8][4];
#pragma unroll
        for (int kk = 0; kk < 8; kk++) {
            qa[kk][0] = Q0[kk * 8 + tig] * 0.125f;
            qa[kk][1] = Q1[kk * 8 + tig] * 0.125f;
            qa[kk][2] = Q0[kk * 8 + tig + 4] * 0.125f;
            qa[kk][3] = Q1[kk * 8 + tig + 4] * 0.125f;
        }
        float oc[8][4];
#pragma unroll
        for (int nt = 0; nt < 8; nt++)
            oc[nt][0] = oc[nt][1] = oc[nt][2] = oc[nt][3] = 0.f;
        float sum0 = 0.f, sum1 = 0.f;

        attn_kblock<8, VTSTR_S>(sKs, sVt, Pw, sPw, qa, oc, sum0, sum1, lane, 0, KPROJ);
        attn_kblock<8, VTSTR_S>(sKs, sVt, Pw, sPw, qa, oc, sum0, sum1, lane, 64, KPROJ);

        sum0 += __shfl_xor_sync(0xffffffffu, sum0, 1);
        sum0 += __shfl_xor_sync(0xffffffffu, sum0, 2);
        sum1 += __shfl_xor_sync(0xffffffffu, sum1, 1);
        sum1 += __shfl_xor_sync(0xffffffffu, sum1, 2);
        float inv0 = 1.f / sum0, inv1 = 1.f / sum1;

        int row0 = q0 + g, row1 = q0 + g + 8;
        if (row0 < NS) {
            float* op = g_O2 + ((size_t)fb * NS + row0) * 512 + h * 64;
#pragma unroll
            for (int nt = 0; nt < 8; nt++)
                *(float2*)(op + nt * 8 + 2 * tig) =
                    make_float2(oc[nt][0] * inv0, oc[nt][1] * inv0);
        }
        if (row1 < NS) {
            float* op = g_O2 + ((size_t)fb * NS + row1) * 512 + h * 64;
#pragma unroll
            for (int nt = 0; nt < 8; nt++)
                *(float2*)(op + nt * 8 + 2 * tig) =
                    make_float2(oc[nt][2] * inv1, oc[nt][3] * inv1);
        }
    }
}

// ---------------- launch -----------------------------------------------------
extern "C" void kernel_launch(void* const* d_in, const int* in_sizes, int n_in,
                              void* d_out, int out_size) {
    const float* x      = (const float*)d_in[0];
    const float* Wqkv_t = (const float*)d_in[1];
    const float* Wo_t   = (const float*)d_in[2];
    const float* Wqkv_s = (const float*)d_in[3];
    const float* Wo_s   = (const float*)d_in[4];
    const float* E      = (const float*)d_in[5];
    const float* W1     = (const float*)d_in[6];
    const float* b1     = (const float*)d_in[7];
    const float* W2     = (const float*)d_in[8];
    const float* b2     = (const float*)d_in[9];
    float* out = (float*)d_out;
    (void)in_sizes; (void)n_in; (void)out_size;

    float *QKV1, *O1, *Y1, *QKV2, *O2, *Y2, *H;
    float *WqkvTt, *WoTt, *WqkvTs, *WoTs, *W1T, *W2T;
    cudaGetSymbolAddress((void**)&QKV1, g_QKV1);
    cudaGetSymbolAddress((void**)&O1, g_O1);
    cudaGetSymbolAddress((void**)&Y1, g_Y1);
    cudaGetSymbolAddress((void**)&QKV2, g_QKV2);
    cudaGetSymbolAddress((void**)&O2, g_O2);
    cudaGetSymbolAddress((void**)&Y2, g_Y2);
    cudaGetSymbolAddress((void**)&H, g_H);
    cudaGetSymbolAddress((void**)&WqkvTt, g_WqkvTt);
    cudaGetSymbolAddress((void**)&WoTt, g_WoTt);
    cudaGetSymbolAddress((void**)&WqkvTs, g_WqkvTs);
    cudaGetSymbolAddress((void**)&WoTs, g_WoTs);
    cudaGetSymbolAddress((void**)&W1T, g_W1T);
    cudaGetSymbolAddress((void**)&W2T, g_W2T);

    cudaFuncSetAttribute(attn_t_mma, cudaFuncAttributeMaxDynamicSharedMemorySize, SMEM_AT);
    cudaFuncSetAttribute(attn_s_fused, cudaFuncAttributeMaxDynamicSharedMemorySize, SMEM_SF);
    cudaFuncSetAttribute((tf32_gemm<0,1,0>), cudaFuncAttributeMaxDynamicSharedMemorySize, GEMM_SMEM);
    cudaFuncSetAttribute((tf32_gemm<1,0,1>), cudaFuncAttributeMaxDynamicSharedMemorySize, GEMM_SMEM);
    cudaFuncSetAttribute((tf32_gemm<0,2,0>), cudaFuncAttributeMaxDynamicSharedMemorySize, GEMM_SMEM);
    cudaFuncSetAttribute((tf32_gemm<1,0,2>), cudaFuncAttributeMaxDynamicSharedMemorySize, GEMM_SMEM);
    cudaFuncSetAttribute((tf32_gemm<2,0,0>), cudaFuncAttributeMaxDynamicSharedMemorySize, GEMM_SMEM);
    cudaFuncSetAttribute((tf32_gemm<3,0,0>), cudaFuncAttributeMaxDynamicSharedMemorySize, GEMM_SMEM);

    // ---- weight transposes ----
    transpose_w<<<dim3(3 * DIMX / 32, DIMX / 32), 256>>>(Wqkv_t, WqkvTt, DIMX, 3 * DIMX);
    transpose_w<<<dim3(DIMX / 32, DIMX / 32), 256>>>(Wo_t, WoTt, DIMX, DIMX);
    transpose_w<<<dim3(3 * DIMX / 32, DIMX / 32), 256>>>(Wqkv_s, WqkvTs, DIMX, 3 * DIMX);
    transpose_w<<<dim3(DIMX / 32, DIMX / 32), 256>>>(Wo_s, WoTs, DIMX, DIMX);
    transpose_w<<<dim3(DFF / 32, DIMX / 32), 256>>>(W1, W1T, DIMX, DFF);
    transpose_w<<<dim3(DIMX / 32, DFF / 32), 256>>>(W2, W2T, DFF, DIMX);

    // ---- temporal stage ----
    tf32_gemm<0,1,0><<<dim3(3 * DIMX / 128, (MT + 127) / 128), 256, GEMM_SMEM>>>(
        x, WqkvTt, QKV1, nullptr, nullptr, MT, 3 * DIMX, DIMX);
    attn_t_mma<<<PATCHES * HEADS, 256, SMEM_AT>>>();
    tf32_gemm<1,0,1><<<dim3(DIMX / 128, (MT + 127) / 128), 256, GEMM_SMEM>>>(
        O1, WoTt, Y1, nullptr, x, MT, DIMX, DIMX);

    // ---- spatial stage ----
    tf32_gemm<0,2,0><<<dim3(3 * DIMX / 128, MS / 128), 256, GEMM_SMEM>>>(
        Y1, WqkvTs, QKV2, nullptr, nullptr, MS, 3 * DIMX, DIMX);
    attn_s_fused<<<FRAMES * HEADS, 256, SMEM_SF>>>(E);
    tf32_gemm<1,0,2><<<dim3(DIMX / 128, MS / 128), 256, GEMM_SMEM>>>(
        O2, WoTs, Y2, nullptr, Y1, MS, DIMX, DIMX);

    // ---- FFN ----
    tf32_gemm<2,0,0><<<dim3(DFF / 128, MS / 128), 256, GEMM_SMEM>>>(
        Y2, W1T, H, b1, nullptr, MS, DFF, DIMX);
    tf32_gemm<3,0,0><<<dim3(DIMX / 128, MS / 128), 256, GEMM_SMEM>>>(
        H, W2T, out, b2, Y2, MS, DIMX, DFF);
}

// round 11
// speedup vs baseline: 1.0420x; 1.0420x over previous
#include <cuda_runtime.h>
#include <math.h>
#include <cstdint>

#define FRAMES 256
#define PATCHES 64
#define DIMX 512
#define HEADS 8
#define DH 64
#define DFF 1024
#define KPROJ 128
#define NT 257              // temporal seq len (cls + 256 frames)
#define NS 65               // spatial seq len (cls + 64 patches)
#define MT (PATCHES * NT)   // 16448 rows temporal
#define MS (FRAMES * NS)    // 16640 rows spatial

// ---------------- scratch (device globals; no allocation allowed) ----------
__device__ float g_QKV1[MT * 3 * DIMX];
__device__ float g_O1[MT * DIMX];
__device__ float g_Y1[MT * DIMX];
__device__ float g_QKV2[MS * 3 * DIMX];
__device__ float g_O2[MS * DIMX];
__device__ float g_Y2[MS * DIMX];
__device__ float g_H[MS * DFF];

// ---------------- row remaps (gathers folded into GEMM loads) ---------------
template <int RM>
__device__ __forceinline__ const float* arow(const float* base, int r) {
    if (RM == 1) {
        int t = r % NT, pb = r / NT;
        int src = (t == 0) ? 0 : (1 + (t - 1) * PATCHES + pb);
        return base + (size_t)src * DIMX;
    } else {
        int s = r % NS, fb = r / NS;
        int srow = (s == 0) ? ((fb & 63) * NT) : ((s - 1) * NT + 1 + fb);
        return base + (size_t)srow * DIMX;
    }
}

// ---------------- tf32 tensor-core GEMM (round-4/8 config, single-sync) -----
#define ASTR 36
#define BSTR 136
#define A_TILE (128 * ASTR)
#define B_TILE (32 * BSTR)
#define GEMM_SMEM ((2 * A_TILE + 2 * B_TILE) * 4)

__device__ __forceinline__ void cp_async16(uint32_t dst, const float* src, int srcsize) {
    asm volatile("cp.async.cg.shared.global [%0], [%1], 16, %2;\n"
                 :: "r"(dst), "l"(src), "r"(srcsize));
}

template <int EPI, int RMA, int RMR>
__global__ void __launch_bounds__(256, 2)
tf32_gemm(const float* __restrict__ A, const float* __restrict__ B,
          float* __restrict__ C, const float* __restrict__ bias,
          const float* __restrict__ R, int M, int N, int K) {
    extern __shared__ float smem[];
    float* As = smem;                    // [2][128][ASTR]
    float* Bs = smem + 2 * A_TILE;       // [2][32][BSTR]
    uint32_t sA = (uint32_t)__cvta_generic_to_shared(As);
    uint32_t sB = (uint32_t)__cvta_generic_to_shared(Bs);

    int tid = threadIdx.x;
    int lane = tid & 31, warp = tid >> 5;
    int wm = warp & 1, wn = warp >> 1;
    int m0 = blockIdx.y * 128;
    int n0 = blockIdx.x * 128;

    int aRow = lane & 15;
    int aCol4 = (lane >> 4) * 4;
    uint32_t aBase[4];
#pragma unroll
    for (int i = 0; i < 4; i++)
        aBase[i] = ((wm * 64 + i * 16 + aRow) * ASTR + aCol4) * 4;

    int tig = lane & 3, g = lane >> 2;
    int bCol = wn * 32 + g;

    float c[4][4][4];
#pragma unroll
    for (int i = 0; i < 4; i++)
#pragma unroll
        for (int j = 0; j < 4; j++)
#pragma unroll
            for (int r = 0; r < 4; r++) c[i][j][r] = 0.f;

    int ntiles = K >> 5;

    auto issue = [&](int t, int buf) {
        int k0 = t << 5;
#pragma unroll
        for (int it = 0; it < 4; it++) {
            int idx = tid + it * 256;
            int row = idx >> 3, ch = (idx & 7) * 4;
            int gr = m0 + row;
            int ok = (gr < M) ? 16 : 0;
            int grc = min(gr, M - 1);
            const float* src;
            if (RMA == 0) src = A + (size_t)grc * K + k0 + ch;
            else          src = arow<RMA>(A, grc) + k0 + ch;
            cp_async16(sA + (buf * A_TILE + row * ASTR + ch) * 4, src, ok);
        }
#pragma unroll
        for (int it = 0; it < 4; it++) {
            int idx = tid + it * 256;
            int row = idx >> 5, ch = (idx & 31) * 4;
            cp_async16(sB + (buf * B_TILE + row * BSTR + ch) * 4,
                       B + (size_t)(k0 + row) * N + n0 + ch, 16);
        }
        asm volatile("cp.async.commit_group;");
    };

    issue(0, 0);

    for (int t = 0; t < ntiles; t++) {
        int buf = t & 1;
        // single-sync pipeline: wait for tile t's loads, barrier, then issue t+1
        asm volatile("cp.async.wait_group 0;");
        __syncthreads();
        if (t + 1 < ntiles) issue(t + 1, (t + 1) & 1);

        const float* Bp = Bs + buf * B_TILE;
        uint32_t sAb = sA + buf * A_TILE * 4;
#pragma unroll
        for (int kk = 0; kk < 32; kk += 8) {
            uint32_t a[4][4];
#pragma unroll
            for (int i = 0; i < 4; i++) {
                asm volatile("ldmatrix.sync.aligned.m8n8.x4.shared.b16 {%0,%1,%2,%3}, [%4];"
                             : "=r"(a[i][0]), "=r"(a[i][1]), "=r"(a[i][2]), "=r"(a[i][3])
                             : "r"(sAb + aBase[i] + kk * 4));
            }
            uint32_t b[4][2];
#pragma unroll
            for (int j = 0; j < 4; j++) {
                b[j][0] = __float_as_uint(Bp[(kk + tig) * BSTR + bCol + j * 8]);
                b[j][1] = __float_as_uint(Bp[(kk + 4 + tig) * BSTR + bCol + j * 8]);
            }
#pragma unroll
            for (int i = 0; i < 4; i++)
#pragma unroll
                for (int j = 0; j < 4; j++) {
                    asm volatile(
                        "mma.sync.aligned.m16n8k8.row.col.f32.tf32.tf32.f32 "
                        "{%0,%1,%2,%3}, {%4,%5,%6,%7}, {%8,%9}, {%0,%1,%2,%3};"
                        : "+f"(c[i][j][0]), "+f"(c[i][j][1]),
                          "+f"(c[i][j][2]), "+f"(c[i][j][3])
                        : "r"(a[i][0]), "r"(a[i][1]), "r"(a[i][2]), "r"(a[i][3]),
                          "r"(b[j][0]), "r"(b[j][1]));
                }
        }
    }

    // epilogue
#pragma unroll
    for (int i = 0; i < 4; i++) {
        int r0 = m0 + wm * 64 + i * 16 + g;
#pragma unroll
        for (int j = 0; j < 4; j++) {
            int col = n0 + wn * 32 + j * 8 + 2 * tig;
#pragma unroll
            for (int half = 0; half < 2; half++) {
                int m = r0 + half * 8;
                if (m >= M) continue;
                float v0 = c[i][j][2 * half + 0];
                float v1 = c[i][j][2 * half + 1];
                if (EPI == 1) {
                    const float* Rrow = (RMR == 0) ? R + (size_t)m * N : arow<RMR>(R, m);
                    v0 += Rrow[col];
                    v1 += Rrow[col + 1];
                } else if (EPI == 2) {
                    v0 += bias[col];
                    v1 += bias[col + 1];
                    v0 = 0.5f * v0 * (1.f + erff(v0 * 0.70710678118654752f));
                    v1 = 0.5f * v1 * (1.f + erff(v1 * 0.70710678118654752f));
                } else if (EPI == 3) {
                    const float* Rrow = R + (size_t)m * N;
                    v0 += bias[col] + Rrow[col];
                    v1 += bias[col + 1] + Rrow[col + 1];
                }
                *(float2*)(C + (size_t)m * N + col) = make_float2(v0, v1);
            }
        }
    }
}

// ---------------- tensor-core attention --------------------------------------
// K stored pair-permuted: orig col c = kk*8 + tig + 4*half at smem col
// p = (c&~7) + 2*(c&3) + ((c>>2)&1), so the mma B pair (tig, tig+4) is one LDS.64.
// KSTR=72: (stride/2) mod 16 = 4 -> phase addrs 4g+tig distinct -> conflict-free.
#define KSTR 72
#define VSTR 72    // PV B-loads: 8tig+g -> 32 distinct banks
#define PSTR 68
#define TKPAD 272
#define SMEM_AT ((TKPAD * KSTR + TKPAD * VSTR + 8 * 16 * PSTR) * 4)

__device__ __forceinline__ void mma8(float (&c)[4], const float (&a)[4],
                                     uint32_t b0, uint32_t b1) {
    asm volatile(
        "mma.sync.aligned.m16n8k8.row.col.f32.tf32.tf32.f32 "
        "{%0,%1,%2,%3}, {%4,%5,%6,%7}, {%8,%9}, {%0,%1,%2,%3};"
        : "+f"(c[0]), "+f"(c[1]), "+f"(c[2]), "+f"(c[3])
        : "r"(__float_as_uint(a[0])), "r"(__float_as_uint(a[1])),
          "r"(__float_as_uint(a[2])), "r"(__float_as_uint(a[3])),
          "r"(b0), "r"(b1));
}

template <int NTILE>
__device__ __forceinline__ void attn_kblock(
    const float* __restrict__ Ksb, const float* __restrict__ Vsb,
    float* __restrict__ Pw,
    const float (&qa)[8][4], float (&oc)[8][4],
    float& sum0, float& sum1,
    int g, int tig, int keybase, int klimit)
{
    float sc[NTILE][4];
#pragma unroll
    for (int nt = 0; nt < NTILE; nt++) {
        sc[nt][0] = sc[nt][1] = sc[nt][2] = sc[nt][3] = 0.f;
        const float* Kp = Ksb + (nt * 8 + g) * KSTR + 2 * tig;
#pragma unroll
        for (int kk = 0; kk < 8; kk++) {
            float2 bv = *(const float2*)(Kp + kk * 8);
            mma8(sc[nt], qa[kk], __float_as_uint(bv.x), __float_as_uint(bv.y));
        }
    }
#pragma unroll
    for (int nt = 0; nt < NTILE; nt++) {
        int key = keybase + nt * 8 + 2 * tig;
        float e0 = (key     < klimit) ? __expf(sc[nt][0]) : 0.f;
        float e1 = (key + 1 < klimit) ? __expf(sc[nt][1]) : 0.f;
        float e2 = (key     < klimit) ? __expf(sc[nt][2]) : 0.f;
        float e3 = (key + 1 < klimit) ? __expf(sc[nt][3]) : 0.f;
        sum0 += e0 + e1;
        sum1 += e2 + e3;
        *(float2*)(Pw + g * PSTR + nt * 8 + 2 * tig)       = make_float2(e0, e1);
        *(float2*)(Pw + (g + 8) * PSTR + nt * 8 + 2 * tig) = make_float2(e2, e3);
    }
    __syncwarp();
    float pa[NTILE][4];
#pragma unroll
    for (int kc = 0; kc < NTILE; kc++) {
        pa[kc][0] = Pw[g * PSTR + kc * 8 + tig];
        pa[kc][1] = Pw[(g + 8) * PSTR + kc * 8 + tig];
        pa[kc][2] = Pw[g * PSTR + kc * 8 + tig + 4];
        pa[kc][3] = Pw[(g + 8) * PSTR + kc * 8 + tig + 4];
    }
#pragma unroll
    for (int nt = 0; nt < 8; nt++) {
#pragma unroll
        for (int kc = 0; kc < NTILE; kc++) {
            const float* Vp = Vsb + (kc * 8 + tig) * VSTR + nt * 8 + g;
            uint32_t b0 = __float_as_uint(Vp[0]);
            uint32_t b1 = __float_as_uint(Vp[4 * VSTR]);
            mma8(oc[nt], pa[kc], b0, b1);
        }
    }
    __syncwarp();
}

// ---------------- temporal attention -----------------------------------------
__global__ void __launch_bounds__(256) attn_t_mma() {
    extern __shared__ float sm[];
    float* Ks = sm;
    float* Vs = Ks + TKPAD * KSTR;
    float* Ps = Vs + TKPAD * VSTR;

    int b = blockIdx.x >> 3, h = blockIdx.x & 7;
    const float* base = g_QKV1 + (size_t)b * NT * 1536;

    for (int i = threadIdx.x; i < TKPAD * 16; i += 256) {
        int t = i >> 4, c4 = (i & 15) * 4;
        float4 kv = make_float4(0.f, 0.f, 0.f, 0.f);
        float4 vv = make_float4(0.f, 0.f, 0.f, 0.f);
        if (t < NT) {
            kv = *(const float4*)(base + (size_t)t * 1536 + 512 + h * 64 + c4);
            vv = *(const float4*)(base + (size_t)t * 1536 + 1024 + h * 64 + c4);
        }
        // pair-permuted K store: cols c4..c4+3 -> grp + {0,2,4,6} + half
        int grp = c4 & ~7, half = (c4 >> 2) & 1;
        float* kd = Ks + t * KSTR + grp + half;
        kd[0] = kv.x; kd[2] = kv.y; kd[4] = kv.z; kd[6] = kv.w;
        float* vd = Vs + t * VSTR + c4;
        vd[0] = vv.x; vd[1] = vv.y; vd[2] = vv.z; vd[3] = vv.w;
    }
    __syncthreads();

    int lane = threadIdx.x & 31, warp = threadIdx.x >> 5;
    int g = lane >> 2, tig = lane & 3;
    float* Pw = Ps + warp * 16 * PSTR;

    for (int qt = warp; qt < 17; qt += 8) {
        int q0 = qt * 16;
        int r0 = min(q0 + g, NT - 1), r1 = min(q0 + g + 8, NT - 1);
        const float* Q0 = base + (size_t)r0 * 1536 + h * 64;
        const float* Q1 = base + (size_t)r1 * 1536 + h * 64;
        float qa[8][4];
#pragma unroll
        for (int kk = 0; kk < 8; kk++) {
            qa[kk][0] = Q0[kk * 8 + tig] * 0.125f;
            qa[kk][1] = Q1[kk * 8 + tig] * 0.125f;
            qa[kk][2] = Q0[kk * 8 + tig + 4] * 0.125f;
            qa[kk][3] = Q1[kk * 8 + tig + 4] * 0.125f;
        }
        float oc[8][4];
#pragma unroll
        for (int nt = 0; nt < 8; nt++)
            oc[nt][0] = oc[nt][1] = oc[nt][2] = oc[nt][3] = 0.f;
        float sum0 = 0.f, sum1 = 0.f;

#pragma unroll
        for (int kb = 0; kb < 4; kb++)
            attn_kblock<8>(Ks + kb * 64 * KSTR, Vs + kb * 64 * VSTR, Pw,
                           qa, oc, sum0, sum1, g, tig, kb * 64, NT);
        attn_kblock<2>(Ks + 256 * KSTR, Vs + 256 * VSTR, Pw,
                       qa, oc, sum0, sum1, g, tig, 256, NT);

        sum0 += __shfl_xor_sync(0xffffffffu, sum0, 1);
        sum0 += __shfl_xor_sync(0xffffffffu, sum0, 2);
        sum1 += __shfl_xor_sync(0xffffffffu, sum1, 1);
        sum1 += __shfl_xor_sync(0xffffffffu, sum1, 2);
        float inv0 = 1.f / sum0, inv1 = 1.f / sum1;

        int row0 = q0 + g, row1 = q0 + g + 8;
        if (row0 < NT) {
            float* op = g_O1 + ((size_t)b * NT + row0) * 512 + h * 64;
#pragma unroll
            for (int nt = 0; nt < 8; nt++)
                *(float2*)(op + nt * 8 + 2 * tig) =
                    make_float2(oc[nt][0] * inv0, oc[nt][1] * inv0);
        }
        if (row1 < NT) {
            float* op = g_O1 + ((size_t)b * NT + row1) * 512 + h * 64;
#pragma unroll
            for (int nt = 0; nt < 8; nt++)
                *(float2*)(op + nt * 8 + 2 * tig) =
                    make_float2(oc[nt][2] * inv1, oc[nt][3] * inv1);
        }
    }
}

// ---------------- fused spatial: E-projection (mma) + attention (mma) --------
#define ETSTR 76
#define KVSTR 72
#define SMEM_SF ((128 * ETSTR + 2 * 72 * KVSTR + KPROJ * KSTR + KPROJ * VSTR + 8 * 16 * PSTR) * 4)

__global__ void __launch_bounds__(256) attn_s_fused(const float* __restrict__ E) {
    extern __shared__ float sm[];
    float* ET   = sm;
    float* Ksrc = ET + 128 * ETSTR;
    float* Vsrc = Ksrc + 72 * KVSTR;
    float* Ks   = Vsrc + 72 * KVSTR;      // [128][KSTR] projected KE (pair-permuted)
    float* Vs   = Ks + KPROJ * KSTR;      // [128][VSTR] projected VE
    float* Ps   = Vs + KPROJ * VSTR;

    int blk = blockIdx.x;
    int fb = blk >> 3, h = blk & 7;
    const float* base = g_QKV2 + (size_t)fb * NS * 1536;

    for (int i = threadIdx.x; i < 128 * 11; i += 256) {
        int kk = i / 11, j = 65 + i % 11;
        ET[kk * ETSTR + j] = 0.f;
    }
    for (int i = threadIdx.x; i < 7 * KVSTR; i += 256) {
        Ksrc[65 * KVSTR + i] = 0.f;
        Vsrc[65 * KVSTR + i] = 0.f;
    }
    for (int i = threadIdx.x; i < NS * 128; i += 256) {
        int j = i >> 7, kk = i & 127;
        ET[kk * ETSTR + j] = E[i];
    }
    for (int i = threadIdx.x; i < NS * 16; i += 256) {
        int j = i >> 4, c4 = (i & 15) * 4;
        float4 kv = *(const float4*)(base + (size_t)j * 1536 + 512 + h * 64 + c4);
        float4 vv = *(const float4*)(base + (size_t)j * 1536 + 1024 + h * 64 + c4);
        *(float4*)(Ksrc + j * KVSTR + c4) = kv;
        *(float4*)(Vsrc + j * KVSTR + c4) = vv;
    }
    __syncthreads();

    int lane = threadIdx.x & 31, warp = threadIdx.x >> 5;
    int g = lane >> 2, tig = lane & 3;

    // phase 1: KE/VE = E^T (128x72) @ K/V (72x64) via mma
    {
        int m0w = warp * 16;
        float ck[8][4], cv[8][4];
#pragma unroll
        for (int nf = 0; nf < 8; nf++) {
            ck[nf][0] = ck[nf][1] = ck[nf][2] = ck[nf][3] = 0.f;
            cv[nf][0] = cv[nf][1] = cv[nf][2] = cv[nf][3] = 0.f;
        }
#pragma unroll
        for (int ks = 0; ks < 9; ks++) {
            int j0 = ks * 8;
            float a[4];
            a[0] = ET[(m0w + g) * ETSTR + j0 + tig];
            a[1] = ET[(m0w + g + 8) * ETSTR + j0 + tig];
            a[2] = ET[(m0w + g) * ETSTR + j0 + tig + 4];
            a[3] = ET[(m0w + g + 8) * ETSTR + j0 + tig + 4];
#pragma unroll
            for (int nf = 0; nf < 8; nf++) {
                const float* Kp = Ksrc + (j0 + tig) * KVSTR + nf * 8 + g;
                mma8(ck[nf], a, __float_as_uint(Kp[0]), __float_as_uint(Kp[4 * KVSTR]));
                const float* Vp = Vsrc + (j0 + tig) * KVSTR + nf * 8 + g;
                mma8(cv[nf], a, __float_as_uint(Vp[0]), __float_as_uint(Vp[4 * KVSTR]));
            }
        }
#pragma unroll
        for (int nf = 0; nf < 8; nf++) {
            int c0 = nf * 8 + 2 * tig;
            int c1 = c0 + 1;
            int p0 = (c0 & ~7) | ((c0 & 3) << 1) | ((c0 >> 2) & 1);
            int p1 = (c1 & ~7) | ((c1 & 3) << 1) | ((c1 >> 2) & 1);
            Ks[(m0w + g) * KSTR + p0]     = ck[nf][0];
            Ks[(m0w + g) * KSTR + p1]     = ck[nf][1];
            Ks[(m0w + g + 8) * KSTR + p0] = ck[nf][2];
            Ks[(m0w + g + 8) * KSTR + p1] = ck[nf][3];
            *(float2*)(Vs + (m0w + g) * VSTR + c0)     = make_float2(cv[nf][0], cv[nf][1]);
            *(float2*)(Vs + (m0w + g + 8) * VSTR + c0) = make_float2(cv[nf][2], cv[nf][3]);
        }
    }
    __syncthreads();

    // phase 2: attention over 128 projected keys
    float* Pw = Ps + warp * 16 * PSTR;
    for (int qt = warp; qt < 5; qt += 8) {
        int q0 = qt * 16;
        int r0 = min(q0 + g, NS - 1), r1 = min(q0 + g + 8, NS - 1);
        const float* Q0 = base + (size_t)r0 * 1536 + h * 64;
        const float* Q1 = base + (size_t)r1 * 1536 + h * 64;
        float qa[8][4];
#pragma unroll
        for (int kk = 0; kk < 8; kk++) {
            qa[kk][0] = Q0[kk * 8 + tig] * 0.125f;
            qa[kk][1] = Q1[kk * 8 + tig] * 0.125f;
            qa[kk][2] = Q0[kk * 8 + tig + 4] * 0.125f;
            qa[kk][3] = Q1[kk * 8 + tig + 4] * 0.125f;
        }
        float oc[8][4];
#pragma unroll
        for (int nt = 0; nt < 8; nt++)
            oc[nt][0] = oc[nt][1] = oc[nt][2] = oc[nt][3] = 0.f;
        float sum0 = 0.f, sum1 = 0.f;

        attn_kblock<8>(Ks, Vs, Pw, qa, oc, sum0, sum1, g, tig, 0, KPROJ);
        attn_kblock<8>(Ks + 64 * KSTR, Vs + 64 * VSTR, Pw,
                       qa, oc, sum0, sum1, g, tig, 64, KPROJ);

        sum0 += __shfl_xor_sync(0xffffffffu, sum0, 1);
        sum0 += __shfl_xor_sync(0xffffffffu, sum0, 2);
        sum1 += __shfl_xor_sync(0xffffffffu, sum1, 1);
        sum1 += __shfl_xor_sync(0xffffffffu, sum1, 2);
        float inv0 = 1.f / sum0, inv1 = 1.f / sum1;

        int row0 = q0 + g, row1 = q0 + g + 8;
        if (row0 < NS) {
            float* op = g_O2 + ((size_t)fb * NS + row0) * 512 + h * 64;
#pragma unroll
            for (int nt = 0; nt < 8; nt++)
                *(float2*)(op + nt * 8 + 2 * tig) =
                    make_float2(oc[nt][0] * inv0, oc[nt][1] * inv0);
        }
        if (row1 < NS) {
            float* op = g_O2 + ((size_t)fb * NS + row1) * 512 + h * 64;
#pragma unroll
            for (int nt = 0; nt < 8; nt++)
                *(float2*)(op + nt * 8 + 2 * tig) =
                    make_float2(oc[nt][2] * inv1, oc[nt][3] * inv1);
        }
    }
}

// ---------------- launch -----------------------------------------------------
extern "C" void kernel_launch(void* const* d_in, const int* in_sizes, int n_in,
                              void* d_out, int out_size) {
    const float* x      = (const float*)d_in[0];
    const float* Wqkv_t = (const float*)d_in[1];
    const float* Wo_t   = (const float*)d_in[2];
    const float* Wqkv_s = (const float*)d_in[3];
    const float* Wo_s   = (const float*)d_in[4];
    const float* E      = (const float*)d_in[5];
    const float* W1     = (const float*)d_in[6];
    const float* b1     = (const float*)d_in[7];
    const float* W2     = (const float*)d_in[8];
    const float* b2     = (const float*)d_in[9];
    float* out = (float*)d_out;
    (void)in_sizes; (void)n_in; (void)out_size;

    float *QKV1, *O1, *Y1, *QKV2, *O2, *Y2, *H;
    cudaGetSymbolAddress((void**)&QKV1, g_QKV1);
    cudaGetSymbolAddress((void**)&O1, g_O1);
    cudaGetSymbolAddress((void**)&Y1, g_Y1);
    cudaGetSymbolAddress((void**)&QKV2, g_QKV2);
    cudaGetSymbolAddress((void**)&O2, g_O2);
    cudaGetSymbolAddress((void**)&Y2, g_Y2);
    cudaGetSymbolAddress((void**)&H, g_H);

    cudaFuncSetAttribute(attn_t_mma, cudaFuncAttributeMaxDynamicSharedMemorySize, SMEM_AT);
    cudaFuncSetAttribute(attn_s_fused, cudaFuncAttributeMaxDynamicSharedMemorySize, SMEM_SF);
    cudaFuncSetAttribute((tf32_gemm<0,1,0>), cudaFuncAttributeMaxDynamicSharedMemorySize, GEMM_SMEM);
    cudaFuncSetAttribute((tf32_gemm<1,0,1>), cudaFuncAttributeMaxDynamicSharedMemorySize, GEMM_SMEM);
    cudaFuncSetAttribute((tf32_gemm<0,2,0>), cudaFuncAttributeMaxDynamicSharedMemorySize, GEMM_SMEM);
    cudaFuncSetAttribute((tf32_gemm<1,0,2>), cudaFuncAttributeMaxDynamicSharedMemorySize, GEMM_SMEM);
    cudaFuncSetAttribute((tf32_gemm<2,0,0>), cudaFuncAttributeMaxDynamicSharedMemorySize, GEMM_SMEM);
    cudaFuncSetAttribute((tf32_gemm<3,0,0>), cudaFuncAttributeMaxDynamicSharedMemorySize, GEMM_SMEM);

    // ---- temporal stage (gather folded into A/R remaps) ----
    tf32_gemm<0,1,0><<<dim3(3 * DIMX / 128, (MT + 127) / 128), 256, GEMM_SMEM>>>(
        x, Wqkv_t, QKV1, nullptr, nullptr, MT, 3 * DIMX, DIMX);
    attn_t_mma<<<PATCHES * HEADS, 256, SMEM_AT>>>();
    tf32_gemm<1,0,1><<<dim3(DIMX / 128, (MT + 127) / 128), 256, GEMM_SMEM>>>(
        O1, Wo_t, Y1, nullptr, x, MT, DIMX, DIMX);

    // ---- spatial stage ----
    tf32_gemm<0,2,0><<<dim3(3 * DIMX / 128, MS / 128), 256, GEMM_SMEM>>>(
        Y1, Wqkv_s, QKV2, nullptr, nullptr, MS, 3 * DIMX, DIMX);
    attn_s_fused<<<FRAMES * HEADS, 256, SMEM_SF>>>(E);
    tf32_gemm<1,0,2><<<dim3(DIMX / 128, MS / 128), 256, GEMM_SMEM>>>(
        O2, Wo_s, Y2, nullptr, Y1, MS, DIMX, DIMX);

    // ---- FFN ----
    tf32_gemm<2,0,0><<<dim3(DFF / 128, MS / 128), 256, GEMM_SMEM>>>(
        Y2, W1, H, b1, nullptr, MS, DFF, DIMX);
    tf32_gemm<3,0,0><<<dim3(DIMX / 128, MS / 128), 256, GEMM_SMEM>>>(
        H, W2, out, b2, Y2, MS, DIMX, DFF);
}

// round 13
// speedup vs baseline: 1.3705x; 1.3152x over previous
#include <cuda_runtime.h>
#include <cuda_fp16.h>
#include <math.h>
#include <cstdint>

#define FRAMES 256
#define PATCHES 64
#define DIMX 512
#define HEADS 8
#define DH 64
#define DFF 1024
#define KPROJ 128
#define NT 257              // temporal seq len (cls + 256 frames)
#define NS 65               // spatial seq len (cls + 64 patches)
#define MT (PATCHES * NT)   // 16448 rows temporal
#define MS (FRAMES * NS)    // 16640 rows spatial

// ---------------- scratch (device globals; no allocation allowed) ----------
__device__ float g_QKV1[MT * 3 * DIMX];
__device__ float g_Y1[MT * DIMX];
__device__ float g_QKV2[MS * 3 * DIMX];
__device__ float g_Y2[MS * DIMX];
// half-precision activations (A operands of GEMMs)
__device__ __half g_xh[(1 + FRAMES * PATCHES) * DIMX];
__device__ __half g_O1h[MT * DIMX];
__device__ __half g_Y1h[MT * DIMX];
__device__ __half g_O2h[MS * DIMX];
__device__ __half g_Y2h[MS * DIMX];
__device__ __half g_Hh[MS * DFF];
// half weights (same [K][N] layout as inputs)
__device__ __half g_Whqt[DIMX * 3 * DIMX];
__device__ __half g_Whot[DIMX * DIMX];
__device__ __half g_Whqs[DIMX * 3 * DIMX];
__device__ __half g_Whos[DIMX * DIMX];
__device__ __half g_Wh1[DIMX * DFF];
__device__ __half g_Wh2[DFF * DIMX];

// ---------------- fp32 -> fp16 convert --------------------------------------
__global__ void cvt_half(const float* __restrict__ in, __half* __restrict__ out,
                         int n4) {
    int i = blockIdx.x * 256 + threadIdx.x;
    if (i >= n4) return;
    float4 v = ((const float4*)in)[i];
    __half2* o = (__half2*)out + 2 * i;
    o[0] = __floats2half2_rn(v.x, v.y);
    o[1] = __floats2half2_rn(v.z, v.w);
}

// ---------------- row remaps (gathers folded into GEMM loads) ---------------
template <int RM, typename T>
__device__ __forceinline__ const T* arow(const T* base, int r) {
    if (RM == 1) {
        int t = r % NT, pb = r / NT;
        int src = (t == 0) ? 0 : (1 + (t - 1) * PATCHES + pb);
        return base + (size_t)src * DIMX;
    } else {
        int s = r % NS, fb = r / NS;
        int srow = (s == 0) ? ((fb & 63) * NT) : ((s - 1) * NT + 1 + fb);
        return base + (size_t)srow * DIMX;
    }
}

__device__ __forceinline__ void cp_async16(uint32_t dst, const void* src, int srcsize) {
    asm volatile("cp.async.cg.shared.global [%0], [%1], 16, %2;\n"
                 :: "r"(dst), "l"(src), "r"(srcsize));
}
__device__ __forceinline__ void ldsm4(uint32_t (&r)[4], uint32_t addr) {
    asm volatile("ldmatrix.sync.aligned.m8n8.x4.shared.b16 {%0,%1,%2,%3}, [%4];"
                 : "=r"(r[0]), "=r"(r[1]), "=r"(r[2]), "=r"(r[3]) : "r"(addr));
}
__device__ __forceinline__ void ldsm4t(uint32_t (&r)[4], uint32_t addr) {
    asm volatile("ldmatrix.sync.aligned.m8n8.x4.trans.shared.b16 {%0,%1,%2,%3}, [%4];"
                 : "=r"(r[0]), "=r"(r[1]), "=r"(r[2]), "=r"(r[3]) : "r"(addr));
}
__device__ __forceinline__ void hmma16(float (&c)[4], const uint32_t (&a)[4],
                                       uint32_t b0, uint32_t b1) {
    asm volatile(
        "mma.sync.aligned.m16n8k16.row.col.f32.f16.f16.f32 "
        "{%0,%1,%2,%3}, {%4,%5,%6,%7}, {%8,%9}, {%0,%1,%2,%3};"
        : "+f"(c[0]), "+f"(c[1]), "+f"(c[2]), "+f"(c[3])
        : "r"(a[0]), "r"(a[1]), "r"(a[2]), "r"(a[3]), "r"(b0), "r"(b1));
}

// ---------------- fp16 tensor-core GEMM --------------------------------------
// C[M,N] = A[M,K](half) @ B[K,N](half). 128x128x32 tiles, 8 warps of 64x32.
// A frags: ldmatrix.x4 (row-major); B frags: ldmatrix.x4.trans on [K][N].
// EPI: 0 none, 1 +R, 2 gelu(+bias), 3 +bias+R.  WH: 0 f32 out, 1 both, 2 half out.
#define ASTRH 40    // halves per A row: 80B = 5x16B (odd) -> conflict-free
#define BSTRH 136   // halves per B row: 272B = 17x16B (odd) -> conflict-free
#define A_TILEH (128 * ASTRH)
#define B_TILEH (32 * BSTRH)
#define HGEMM_SMEM ((2 * A_TILEH + 2 * B_TILEH) * 2)

template <int EPI, int RMA, int RMR, int WH>
__global__ void __launch_bounds__(256, 2)
hgemm(const __half* __restrict__ A, const __half* __restrict__ B,
      float* __restrict__ Cf, __half* __restrict__ Ch,
      const float* __restrict__ bias, const float* __restrict__ R,
      int M, int N, int K) {
    extern __shared__ __half smh[];
    uint32_t sA = (uint32_t)__cvta_generic_to_shared(smh);
    uint32_t sB = sA + 2 * A_TILEH * 2;

    int tid = threadIdx.x;
    int lane = tid & 31, warp = tid >> 5;
    int wm = warp & 1, wn = warp >> 1;
    int m0 = blockIdx.y * 128;
    int n0 = blockIdx.x * 128;

    // A ldmatrix bases: row = lane&15, col16B = (lane>>4)
    uint32_t aBase[4];
#pragma unroll
    for (int i = 0; i < 4; i++)
        aBase[i] = ((wm * 64 + i * 16 + (lane & 15)) * ASTRH + (lane >> 4) * 8) * 2;
    // B trans ldmatrix bases (q covers n-chunks 2q,2q+1): krow = lane&15
    uint32_t bBase[2];
#pragma unroll
    for (int q = 0; q < 2; q++)
        bBase[q] = ((lane & 15) * BSTRH + wn * 32 + q * 16 + (lane >> 4) * 8) * 2;

    int tig = lane & 3, g = lane >> 2;

    float c[4][4][4];
#pragma unroll
    for (int i = 0; i < 4; i++)
#pragma unroll
        for (int j = 0; j < 4; j++)
#pragma unroll
            for (int r = 0; r < 4; r++) c[i][j][r] = 0.f;

    int ntiles = K >> 5;

    auto issue = [&](int t, int buf) {
        int k0 = t << 5;
#pragma unroll
        for (int it = 0; it < 2; it++) {       // A: 128 rows x 4 chunks of 8 halves
            int idx = tid + it * 256;
            int row = idx >> 2, ch = (idx & 3) * 8;
            int gr = m0 + row;
            int ok = (gr < M) ? 16 : 0;
            int grc = min(gr, M - 1);
            const __half* src;
            if (RMA == 0) src = A + (size_t)grc * K + k0 + ch;
            else          src = arow<RMA>(A, grc) + k0 + ch;
            cp_async16(sA + (buf * A_TILEH + row * ASTRH + ch) * 2, src, ok);
        }
#pragma unroll
        for (int it = 0; it < 2; it++) {       // B: 32 rows x 16 chunks of 8 halves
            int idx = tid + it * 256;
            int row = idx >> 4, ch = (idx & 15) * 8;
            cp_async16(sB + (buf * B_TILEH + row * BSTRH + ch) * 2,
                       B + (size_t)(k0 + row) * N + n0 + ch, 16);
        }
        asm volatile("cp.async.commit_group;");
    };

    issue(0, 0);

    for (int t = 0; t < ntiles; t++) {
        int buf = t & 1;
        asm volatile("cp.async.wait_group 0;");
        __syncthreads();
        if (t + 1 < ntiles) issue(t + 1, (t + 1) & 1);

        uint32_t sAb = sA + buf * A_TILEH * 2;
        uint32_t sBb = sB + buf * B_TILEH * 2;
#pragma unroll
        for (int ks = 0; ks < 2; ks++) {       // two k16 steps per 32-k tile
            uint32_t a[4][4];
#pragma unroll
            for (int i = 0; i < 4; i++)
                ldsm4(a[i], sAb + aBase[i] + ks * 32);       // +16 halves
            uint32_t bf[2][4];
#pragma unroll
            for (int q = 0; q < 2; q++)
                ldsm4t(bf[q], sBb + bBase[q] + ks * 16 * BSTRH * 2);
#pragma unroll
            for (int i = 0; i < 4; i++)
#pragma unroll
                for (int j = 0; j < 4; j++) {
                    int q = j >> 1, o = (j & 1) * 2;
                    hmma16(c[i][j], a[i], bf[q][o], bf[q][o + 1]);
                }
        }
    }

    // epilogue
#pragma unroll
    for (int i = 0; i < 4; i++) {
        int r0 = m0 + wm * 64 + i * 16 + g;
#pragma unroll
        for (int j = 0; j < 4; j++) {
            int col = n0 + wn * 32 + j * 8 + 2 * tig;
#pragma unroll
            for (int half = 0; half < 2; half++) {
                int m = r0 + half * 8;
                if (m >= M) continue;
                float v0 = c[i][j][2 * half + 0];
                float v1 = c[i][j][2 * half + 1];
                if (EPI == 1) {
                    const float* Rrow = (RMR == 0) ? R + (size_t)m * N
                                                   : arow<RMR>(R, m);
                    v0 += Rrow[col];
                    v1 += Rrow[col + 1];
                } else if (EPI == 2) {
                    v0 += bias[col];
                    v1 += bias[col + 1];
                    v0 = 0.5f * v0 * (1.f + erff(v0 * 0.70710678118654752f));
                    v1 = 0.5f * v1 * (1.f + erff(v1 * 0.70710678118654752f));
                } else if (EPI == 3) {
                    const float* Rrow = R + (size_t)m * N;
                    v0 += bias[col] + Rrow[col];
                    v1 += bias[col + 1] + Rrow[col + 1];
                }
                if (WH != 2)
                    *(float2*)(Cf + (size_t)m * N + col) = make_float2(v0, v1);
                if (WH >= 1)
                    *(__half2*)(Ch + (size_t)m * N + col) = __floats2half2_rn(v0, v1);
            }
        }
    }
}

// ---------------- tensor-core attention (round-8 proven form) ----------------
#define KSTR 68    // QK B-loads: 32 distinct banks (4g+tig)
#define VSTR 72    // PV B-loads: 32 distinct banks (8tig+g)
#define PSTR 68
#define TKPAD 272
#define SMEM_AT ((TKPAD * KSTR + TKPAD * VSTR + 8 * 16 * PSTR) * 4)

__device__ __forceinline__ void mma8(float (&c)[4], const float (&a)[4],
                                     uint32_t b0, uint32_t b1) {
    asm volatile(
        "mma.sync.aligned.m16n8k8.row.col.f32.tf32.tf32.f32 "
        "{%0,%1,%2,%3}, {%4,%5,%6,%7}, {%8,%9}, {%0,%1,%2,%3};"
        : "+f"(c[0]), "+f"(c[1]), "+f"(c[2]), "+f"(c[3])
        : "r"(__float_as_uint(a[0])), "r"(__float_as_uint(a[1])),
          "r"(__float_as_uint(a[2])), "r"(__float_as_uint(a[3])),
          "r"(b0), "r"(b1));
}

template <int NTILE>
__device__ __forceinline__ void attn_kblock(
    const float* __restrict__ Ksb, const float* __restrict__ Vsb,
    float* __restrict__ Pw,
    const float (&qa)[8][4], float (&oc)[8][4],
    float& sum0, float& sum1,
    int g, int tig, int keybase, int klimit)
{
    float sc[NTILE][4];
#pragma unroll
    for (int nt = 0; nt < NTILE; nt++) {
        sc[nt][0] = sc[nt][1] = sc[nt][2] = sc[nt][3] = 0.f;
        const float* Kp = Ksb + (nt * 8 + g) * KSTR;
#pragma unroll
        for (int kk = 0; kk < 8; kk++) {
            uint32_t b0 = __float_as_uint(Kp[kk * 8 + tig]);
            uint32_t b1 = __float_as_uint(Kp[kk * 8 + tig + 4]);
            mma8(sc[nt], qa[kk], b0, b1);
        }
    }
#pragma unroll
    for (int nt = 0; nt < NTILE; nt++) {
        int key = keybase + nt * 8 + 2 * tig;
        float e0 = (key     < klimit) ? __expf(sc[nt][0]) : 0.f;
        float e1 = (key + 1 < klimit) ? __expf(sc[nt][1]) : 0.f;
        float e2 = (key     < klimit) ? __expf(sc[nt][2]) : 0.f;
        float e3 = (key + 1 < klimit) ? __expf(sc[nt][3]) : 0.f;
        sum0 += e0 + e1;
        sum1 += e2 + e3;
        *(float2*)(Pw + g * PSTR + nt * 8 + 2 * tig)       = make_float2(e0, e1);
        *(float2*)(Pw + (g + 8) * PSTR + nt * 8 + 2 * tig) = make_float2(e2, e3);
    }
    __syncwarp();
    float pa[NTILE][4];
#pragma unroll
    for (int kc = 0; kc < NTILE; kc++) {
        pa[kc][0] = Pw[g * PSTR + kc * 8 + tig];
        pa[kc][1] = Pw[(g + 8) * PSTR + kc * 8 + tig];
        pa[kc][2] = Pw[g * PSTR + kc * 8 + tig + 4];
        pa[kc][3] = Pw[(g + 8) * PSTR + kc * 8 + tig + 4];
    }
#pragma unroll
    for (int nt = 0; nt < 8; nt++) {
#pragma unroll
        for (int kc = 0; kc < NTILE; kc++) {
            const float* Vp = Vsb + (kc * 8 + tig) * VSTR + nt * 8 + g;
            uint32_t b0 = __float_as_uint(Vp[0]);
            uint32_t b1 = __float_as_uint(Vp[4 * VSTR]);
            mma8(oc[nt], pa[kc], b0, b1);
        }
    }
    __syncwarp();
}

// ---------------- temporal attention (writes O1 as half) ---------------------
__global__ void __launch_bounds__(256) attn_t_mma() {
    extern __shared__ float sm[];
    float* Ks = sm;
    float* Vs = Ks + TKPAD * KSTR;
    float* Ps = Vs + TKPAD * VSTR;

    int b = blockIdx.x >> 3, h = blockIdx.x & 7;
    const float* base = g_QKV1 + (size_t)b * NT * 1536;

    for (int i = threadIdx.x; i < TKPAD * 16; i += 256) {
        int t = i >> 4, c4 = (i & 15) * 4;
        float4 kv = make_float4(0.f, 0.f, 0.f, 0.f);
        float4 vv = make_float4(0.f, 0.f, 0.f, 0.f);
        if (t < NT) {
            kv = *(const float4*)(base + (size_t)t * 1536 + 512 + h * 64 + c4);
            vv = *(const float4*)(base + (size_t)t * 1536 + 1024 + h * 64 + c4);
        }
        float* kd = Ks + t * KSTR + c4;
        kd[0] = kv.x; kd[1] = kv.y; kd[2] = kv.z; kd[3] = kv.w;
        float* vd = Vs + t * VSTR + c4;
        vd[0] = vv.x; vd[1] = vv.y; vd[2] = vv.z; vd[3] = vv.w;
    }
    __syncthreads();

    int lane = threadIdx.x & 31, warp = threadIdx.x >> 5;
    int g = lane >> 2, tig = lane & 3;
    float* Pw = Ps + warp * 16 * PSTR;

    for (int qt = warp; qt < 17; qt += 8) {
        int q0 = qt * 16;
        int r0 = min(q0 + g, NT - 1), r1 = min(q0 + g + 8, NT - 1);
        const float* Q0 = base + (size_t)r0 * 1536 + h * 64;
        const float* Q1 = base + (size_t)r1 * 1536 + h * 64;
        float qa[8][4];
#pragma unroll
        for (int kk = 0; kk < 8; kk++) {
            qa[kk][0] = Q0[kk * 8 + tig] * 0.125f;
            qa[kk][1] = Q1[kk * 8 + tig] * 0.125f;
            qa[kk][2] = Q0[kk * 8 + tig + 4] * 0.125f;
            qa[kk][3] = Q1[kk * 8 + tig + 4] * 0.125f;
        }
        float oc[8][4];
#pragma unroll
        for (int nt = 0; nt < 8; nt++)
            oc[nt][0] = oc[nt][1] = oc[nt][2] = oc[nt][3] = 0.f;
        float sum0 = 0.f, sum1 = 0.f;

#pragma unroll
        for (int kb = 0; kb < 4; kb++)
            attn_kblock<8>(Ks + kb * 64 * KSTR, Vs + kb * 64 * VSTR, Pw,
                           qa, oc, sum0, sum1, g, tig, kb * 64, NT);
        attn_kblock<2>(Ks + 256 * KSTR, Vs + 256 * VSTR, Pw,
                       qa, oc, sum0, sum1, g, tig, 256, NT);

        sum0 += __shfl_xor_sync(0xffffffffu, sum0, 1);
        sum0 += __shfl_xor_sync(0xffffffffu, sum0, 2);
        sum1 += __shfl_xor_sync(0xffffffffu, sum1, 1);
        sum1 += __shfl_xor_sync(0xffffffffu, sum1, 2);
        float inv0 = 1.f / sum0, inv1 = 1.f / sum1;

        int row0 = q0 + g, row1 = q0 + g + 8;
        if (row0 < NT) {
            __half* op = g_O1h + ((size_t)b * NT + row0) * 512 + h * 64;
#pragma unroll
            for (int nt = 0; nt < 8; nt++)
                *(__half2*)(op + nt * 8 + 2 * tig) =
                    __floats2half2_rn(oc[nt][0] * inv0, oc[nt][1] * inv0);
        }
        if (row1 < NT) {
            __half* op = g_O1h + ((size_t)b * NT + row1) * 512 + h * 64;
#pragma unroll
            for (int nt = 0; nt < 8; nt++)
                *(__half2*)(op + nt * 8 + 2 * tig) =
                    __floats2half2_rn(oc[nt][2] * inv1, oc[nt][3] * inv1);
        }
    }
}

// ---------------- fused spatial: E-projection + attention (O2 half out) -----
#define ETSTR 76
#define KVSTR 72
#define SMEM_SF ((128 * ETSTR + 2 * 72 * KVSTR + KPROJ * KSTR + KPROJ * VSTR + 8 * 16 * PSTR) * 4)

__global__ void __launch_bounds__(256) attn_s_fused(const float* __restrict__ E) {
    extern __shared__ float sm[];
    float* ET   = sm;
    float* Ksrc = ET + 128 * ETSTR;
    float* Vsrc = Ksrc + 72 * KVSTR;
    float* Ks   = Vsrc + 72 * KVSTR;
    float* Vs   = Ks + KPROJ * KSTR;
    float* Ps   = Vs + KPROJ * VSTR;

    int blk = blockIdx.x;
    int fb = blk >> 3, h = blk & 7;
    const float* base = g_QKV2 + (size_t)fb * NS * 1536;

    for (int i = threadIdx.x; i < 128 * 11; i += 256) {
        int kk = i / 11, j = 65 + i % 11;
        ET[kk * ETSTR + j] = 0.f;
    }
    for (int i = threadIdx.x; i < 7 * KVSTR; i += 256) {
        Ksrc[65 * KVSTR + i] = 0.f;
        Vsrc[65 * KVSTR + i] = 0.f;
    }
    for (int i = threadIdx.x; i < NS * 128; i += 256) {
        int j = i >> 7, kk = i & 127;
        ET[kk * ETSTR + j] = E[i];
    }
    for (int i = threadIdx.x; i < NS * 16; i += 256) {
        int j = i >> 4, c4 = (i & 15) * 4;
        float4 kv = *(const float4*)(base + (size_t)j * 1536 + 512 + h * 64 + c4);
        float4 vv = *(const float4*)(base + (size_t)j * 1536 + 1024 + h * 64 + c4);
        *(float4*)(Ksrc + j * KVSTR + c4) = kv;
        *(float4*)(Vsrc + j * KVSTR + c4) = vv;
    }
    __syncthreads();

    int lane = threadIdx.x & 31, warp = threadIdx.x >> 5;
    int g = lane >> 2, tig = lane & 3;

    // phase 1: KE/VE = E^T @ K/V via mma
    {
        int m0w = warp * 16;
        float ck[8][4], cv[8][4];
#pragma unroll
        for (int nf = 0; nf < 8; nf++) {
            ck[nf][0] = ck[nf][1] = ck[nf][2] = ck[nf][3] = 0.f;
            cv[nf][0] = cv[nf][1] = cv[nf][2] = cv[nf][3] = 0.f;
        }
#pragma unroll
        for (int ks = 0; ks < 9; ks++) {
            int j0 = ks * 8;
            float a[4];
            a[0] = ET[(m0w + g) * ETSTR + j0 + tig];
            a[1] = ET[(m0w + g + 8) * ETSTR + j0 + tig];
            a[2] = ET[(m0w + g) * ETSTR + j0 + tig + 4];
            a[3] = ET[(m0w + g + 8) * ETSTR + j0 + tig + 4];
#pragma unroll
            for (int nf = 0; nf < 8; nf++) {
                const float* Kp = Ksrc + (j0 + tig) * KVSTR + nf * 8 + g;
                mma8(ck[nf], a, __float_as_uint(Kp[0]), __float_as_uint(Kp[4 * KVSTR]));
                const float* Vp = Vsrc + (j0 + tig) * KVSTR + nf * 8 + g;
                mma8(cv[nf], a, __float_as_uint(Vp[0]), __float_as_uint(Vp[4 * KVSTR]));
            }
        }
#pragma unroll
        for (int nf = 0; nf < 8; nf++) {
            int col = nf * 8 + 2 * tig;
            *(float2*)(Ks + (m0w + g) * KSTR + col)     = make_float2(ck[nf][0], ck[nf][1]);
            *(float2*)(Ks + (m0w + g + 8) * KSTR + col) = make_float2(ck[nf][2], ck[nf][3]);
            *(float2*)(Vs + (m0w + g) * VSTR + col)     = make_float2(cv[nf][0], cv[nf][1]);
            *(float2*)(Vs + (m0w + g + 8) * VSTR + col) = make_float2(cv[nf][2], cv[nf][3]);
        }
    }
    __syncthreads();

    // phase 2: attention over 128 projected keys
    float* Pw = Ps + warp * 16 * PSTR;
    for (int qt = warp; qt < 5; qt += 8) {
        int q0 = qt * 16;
        int r0 = min(q0 + g, NS - 1), r1 = min(q0 + g + 8, NS - 1);
        const float* Q0 = base + (size_t)r0 * 1536 + h * 64;
        const float* Q1 = base + (size_t)r1 * 1536 + h * 64;
        float qa[8][4];
#pragma unroll
        for (int kk = 0; kk < 8; kk++) {
            qa[kk][0] = Q0[kk * 8 + tig] * 0.125f;
            qa[kk][1] = Q1[kk * 8 + tig] * 0.125f;
            qa[kk][2] = Q0[kk * 8 + tig + 4] * 0.125f;
            qa[kk][3] = Q1[kk * 8 + tig + 4] * 0.125f;
        }
        float oc[8][4];
#pragma unroll
        for (int nt = 0; nt < 8; nt++)
            oc[nt][0] = oc[nt][1] = oc[nt][2] = oc[nt][3] = 0.f;
        float sum0 = 0.f, sum1 = 0.f;

        attn_kblock<8>(Ks, Vs, Pw, qa, oc, sum0, sum1, g, tig, 0, KPROJ);
        attn_kblock<8>(Ks + 64 * KSTR, Vs + 64 * VSTR, Pw,
                       qa, oc, sum0, sum1, g, tig, 64, KPROJ);

        sum0 += __shfl_xor_sync(0xffffffffu, sum0, 1);
        sum0 += __shfl_xor_sync(0xffffffffu, sum0, 2);
        sum1 += __shfl_xor_sync(0xffffffffu, sum1, 1);
        sum1 += __shfl_xor_sync(0xffffffffu, sum1, 2);
        float inv0 = 1.f / sum0, inv1 = 1.f / sum1;

        int row0 = q0 + g, row1 = q0 + g + 8;
        if (row0 < NS) {
            __half* op = g_O2h + ((size_t)fb * NS + row0) * 512 + h * 64;
#pragma unroll
            for (int nt = 0; nt < 8; nt++)
                *(__half2*)(op + nt * 8 + 2 * tig) =
                    __floats2half2_rn(oc[nt][0] * inv0, oc[nt][1] * inv0);
        }
        if (row1 < NS) {
            __half* op = g_O2h + ((size_t)fb * NS + row1) * 512 + h * 64;
#pragma unroll
            for (int nt = 0; nt < 8; nt++)
                *(__half2*)(op + nt * 8 + 2 * tig) =
                    __floats2half2_rn(oc[nt][2] * inv1, oc[nt][3] * inv1);
        }
    }
}

// ---------------- launch -----------------------------------------------------
extern "C" void kernel_launch(void* const* d_in, const int* in_sizes, int n_in,
                              void* d_out, int out_size) {
    const float* x      = (const float*)d_in[0];
    const float* Wqkv_t = (const float*)d_in[1];
    const float* Wo_t   = (const float*)d_in[2];
    const float* Wqkv_s = (const float*)d_in[3];
    const float* Wo_s   = (const float*)d_in[4];
    const float* E      = (const float*)d_in[5];
    const float* W1     = (const float*)d_in[6];
    const float* b1     = (const float*)d_in[7];
    const float* W2     = (const float*)d_in[8];
    const float* b2     = (const float*)d_in[9];
    float* out = (float*)d_out;
    (void)in_sizes; (void)n_in; (void)out_size;

    float *QKV1, *Y1, *QKV2, *Y2;
    __half *xh, *O1h, *Y1h, *O2h, *Y2h, *Hh;
    __half *Whqt, *Whot, *Whqs, *Whos, *Wh1, *Wh2;
    cudaGetSymbolAddress((void**)&QKV1, g_QKV1);
    cudaGetSymbolAddress((void**)&Y1, g_Y1);
    cudaGetSymbolAddress((void**)&QKV2, g_QKV2);
    cudaGetSymbolAddress((void**)&Y2, g_Y2);
    cudaGetSymbolAddress((void**)&xh, g_xh);
    cudaGetSymbolAddress((void**)&O1h, g_O1h);
    cudaGetSymbolAddress((void**)&Y1h, g_Y1h);
    cudaGetSymbolAddress((void**)&O2h, g_O2h);
    cudaGetSymbolAddress((void**)&Y2h, g_Y2h);
    cudaGetSymbolAddress((void**)&Hh, g_Hh);
    cudaGetSymbolAddress((void**)&Whqt, g_Whqt);
    cudaGetSymbolAddress((void**)&Whot, g_Whot);
    cudaGetSymbolAddress((void**)&Whqs, g_Whqs);
    cudaGetSymbolAddress((void**)&Whos, g_Whos);
    cudaGetSymbolAddress((void**)&Wh1, g_Wh1);
    cudaGetSymbolAddress((void**)&Wh2, g_Wh2);

    cudaFuncSetAttribute(attn_t_mma, cudaFuncAttributeMaxDynamicSharedMemorySize, SMEM_AT);
    cudaFuncSetAttribute(attn_s_fused, cudaFuncAttributeMaxDynamicSharedMemorySize, SMEM_SF);

    // ---- fp16 conversions ----
    auto cvt = [&](const float* src, __half* dst, int n) {
        int n4 = n / 4;
        cvt_half<<<(n4 + 255) / 256, 256>>>(src, dst, n4);
    };
    cvt(x, xh, (1 + FRAMES * PATCHES) * DIMX);
    cvt(Wqkv_t, Whqt, DIMX * 3 * DIMX);
    cvt(Wo_t, Whot, DIMX * DIMX);
    cvt(Wqkv_s, Whqs, DIMX * 3 * DIMX);
    cvt(Wo_s, Whos, DIMX * DIMX);
    cvt(W1, Wh1, DIMX * DFF);
    cvt(W2, Wh2, DFF * DIMX);

    // ---- temporal stage ----
    hgemm<0,1,0,0><<<dim3(3 * DIMX / 128, (MT + 127) / 128), 256, HGEMM_SMEM>>>(
        xh, Whqt, QKV1, nullptr, nullptr, nullptr, MT, 3 * DIMX, DIMX);
    attn_t_mma<<<PATCHES * HEADS, 256, SMEM_AT>>>();
    hgemm<1,0,1,1><<<dim3(DIMX / 128, (MT + 127) / 128), 256, HGEMM_SMEM>>>(
        O1h, Whot, Y1, Y1h, nullptr, x, MT, DIMX, DIMX);

    // ---- spatial stage ----
    hgemm<0,2,0,0><<<dim3(3 * DIMX / 128, MS / 128), 256, HGEMM_SMEM>>>(
        Y1h, Whqs, QKV2, nullptr, nullptr, nullptr, MS, 3 * DIMX, DIMX);
    attn_s_fused<<<FRAMES * HEADS, 256, SMEM_SF>>>(E);
    hgemm<1,0,2,1><<<dim3(DIMX / 128, MS / 128), 256, HGEMM_SMEM>>>(
        O2h, Whos, Y2, Y2h, nullptr, Y1, MS, DIMX, DIMX);

    // ---- FFN ----
    hgemm<2,0,0,2><<<dim3(DFF / 128, MS / 128), 256, HGEMM_SMEM>>>(
        Y2h, Wh1, nullptr, Hh, b1, nullptr, MS, DFF, DIMX);
    hgemm<3,0,0,0><<<dim3(DIMX / 128, MS / 128), 256, HGEMM_SMEM>>>(
        Hh, Wh2, out, nullptr, b2, Y2, MS, DIMX, DFF);
}

// round 16
// speedup vs baseline: 1.6878x; 1.2316x over previous
#include <cuda_runtime.h>
#include <cuda_fp16.h>
#include <math.h>
#include <cstdint>

#define FRAMES 256
#define PATCHES 64
#define DIMX 512
#define HEADS 8
#define DH 64
#define DFF 1024
#define KPROJ 128
#define NT 257              // temporal seq len (cls + 256 frames)
#define NS 65               // spatial seq len (cls + 64 patches)
#define MT (PATCHES * NT)   // 16448 rows temporal
#define MS (FRAMES * NS)    // 16640 rows spatial

// ---------------- scratch (device globals; no allocation allowed) ----------
__device__ float g_Y1[MT * DIMX];
__device__ float g_Y2[MS * DIMX];
__device__ __half g_QKV1h[MT * 3 * DIMX];
__device__ __half g_QKV2h[MS * 3 * DIMX];
__device__ __half g_xh[(1 + FRAMES * PATCHES) * DIMX];
__device__ __half g_O1h[MT * DIMX];
__device__ __half g_Y1h[MT * DIMX];
__device__ __half g_O2h[MS * DIMX];
__device__ __half g_Y2h[MS * DIMX];
__device__ __half g_Hh[MS * DFF];
__device__ __half g_Whqt[DIMX * 3 * DIMX];
__device__ __half g_Whot[DIMX * DIMX];
__device__ __half g_Whqs[DIMX * 3 * DIMX];
__device__ __half g_Whos[DIMX * DIMX];
__device__ __half g_Wh1[DIMX * DFF];
__device__ __half g_Wh2[DFF * DIMX];

// ---------------- fp32 -> fp16 convert --------------------------------------
__global__ void cvt_half(const float* __restrict__ in, __half* __restrict__ out,
                         int n4) {
    int i = blockIdx.x * 256 + threadIdx.x;
    if (i >= n4) return;
    float4 v = ((const float4*)in)[i];
    __half2* o = (__half2*)out + 2 * i;
    o[0] = __floats2half2_rn(v.x, v.y);
    o[1] = __floats2half2_rn(v.z, v.w);
}

// ---------------- row remaps (gathers folded into GEMM loads) ---------------
template <int RM, typename T>
__device__ __forceinline__ const T* arow(const T* base, int r) {
    if (RM == 1) {
        int t = r % NT, pb = r / NT;
        int src = (t == 0) ? 0 : (1 + (t - 1) * PATCHES + pb);
        return base + (size_t)src * DIMX;
    } else {
        int s = r % NS, fb = r / NS;
        int srow = (s == 0) ? ((fb & 63) * NT) : ((s - 1) * NT + 1 + fb);
        return base + (size_t)srow * DIMX;
    }
}

__device__ __forceinline__ void cp_async16(uint32_t dst, const void* src, int srcsize) {
    asm volatile("cp.async.cg.shared.global [%0], [%1], 16, %2;\n"
                 :: "r"(dst), "l"(src), "r"(srcsize));
}
__device__ __forceinline__ void ldsm4(uint32_t (&r)[4], uint32_t addr) {
    asm volatile("ldmatrix.sync.aligned.m8n8.x4.shared.b16 {%0,%1,%2,%3}, [%4];"
                 : "=r"(r[0]), "=r"(r[1]), "=r"(r[2]), "=r"(r[3]) : "r"(addr));
}
__device__ __forceinline__ void ldsm4t(uint32_t (&r)[4], uint32_t addr) {
    asm volatile("ldmatrix.sync.aligned.m8n8.x4.trans.shared.b16 {%0,%1,%2,%3}, [%4];"
                 : "=r"(r[0]), "=r"(r[1]), "=r"(r[2]), "=r"(r[3]) : "r"(addr));
}
__device__ __forceinline__ void hmma16(float (&c)[4], const uint32_t (&a)[4],
                                       uint32_t b0, uint32_t b1) {
    asm volatile(
        "mma.sync.aligned.m16n8k16.row.col.f32.f16.f16.f32 "
        "{%0,%1,%2,%3}, {%4,%5,%6,%7}, {%8,%9}, {%0,%1,%2,%3};"
        : "+f"(c[0]), "+f"(c[1]), "+f"(c[2]), "+f"(c[3])
        : "r"(a[0]), "r"(a[1]), "r"(a[2]), "r"(a[3]), "r"(b0), "r"(b1));
}
__device__ __forceinline__ void mma8(float (&c)[4], const float (&a)[4],
                                     uint32_t b0, uint32_t b1) {
    asm volatile(
        "mma.sync.aligned.m16n8k8.row.col.f32.tf32.tf32.f32 "
        "{%0,%1,%2,%3}, {%4,%5,%6,%7}, {%8,%9}, {%0,%1,%2,%3};"
        : "+f"(c[0]), "+f"(c[1]), "+f"(c[2]), "+f"(c[3])
        : "r"(__float_as_uint(a[0])), "r"(__float_as_uint(a[1])),
          "r"(__float_as_uint(a[2])), "r"(__float_as_uint(a[3])),
          "r"(b0), "r"(b1));
}

// ---------------- fp16 tensor-core GEMM (round-13 proven) --------------------
#define ASTRH 40
#define BSTRH 136
#define A_TILEH (128 * ASTRH)
#define B_TILEH (32 * BSTRH)
#define HGEMM_SMEM ((2 * A_TILEH + 2 * B_TILEH) * 2)

template <int EPI, int RMA, int RMR, int WH>
__global__ void __launch_bounds__(256, 2)
hgemm(const __half* __restrict__ A, const __half* __restrict__ B,
      float* __restrict__ Cf, __half* __restrict__ Ch,
      const float* __restrict__ bias, const float* __restrict__ R,
      int M, int N, int K) {
    extern __shared__ __half smh[];
    uint32_t sA = (uint32_t)__cvta_generic_to_shared(smh);
    uint32_t sB = sA + 2 * A_TILEH * 2;

    int tid = threadIdx.x;
    int lane = tid & 31, warp = tid >> 5;
    int wm = warp & 1, wn = warp >> 1;
    int m0 = blockIdx.y * 128;
    int n0 = blockIdx.x * 128;

    uint32_t aBase[4];
#pragma unroll
    for (int i = 0; i < 4; i++)
        aBase[i] = ((wm * 64 + i * 16 + (lane & 15)) * ASTRH + (lane >> 4) * 8) * 2;
    uint32_t bBase[2];
#pragma unroll
    for (int q = 0; q < 2; q++)
        bBase[q] = ((lane & 15) * BSTRH + wn * 32 + q * 16 + (lane >> 4) * 8) * 2;

    int tig = lane & 3, g = lane >> 2;

    float c[4][4][4];
#pragma unroll
    for (int i = 0; i < 4; i++)
#pragma unroll
        for (int j = 0; j < 4; j++)
#pragma unroll
            for (int r = 0; r < 4; r++) c[i][j][r] = 0.f;

    int ntiles = K >> 5;

    auto issue = [&](int t, int buf) {
        int k0 = t << 5;
#pragma unroll
        for (int it = 0; it < 2; it++) {
            int idx = tid + it * 256;
            int row = idx >> 2, ch = (idx & 3) * 8;
            int gr = m0 + row;
            int ok = (gr < M) ? 16 : 0;
            int grc = min(gr, M - 1);
            const __half* src;
            if (RMA == 0) src = A + (size_t)grc * K + k0 + ch;
            else          src = arow<RMA>(A, grc) + k0 + ch;
            cp_async16(sA + (buf * A_TILEH + row * ASTRH + ch) * 2, src, ok);
        }
#pragma unroll
        for (int it = 0; it < 2; it++) {
            int idx = tid + it * 256;
            int row = idx >> 4, ch = (idx & 15) * 8;
            cp_async16(sB + (buf * B_TILEH + row * BSTRH + ch) * 2,
                       B + (size_t)(k0 + row) * N + n0 + ch, 16);
        }
        asm volatile("cp.async.commit_group;");
    };

    issue(0, 0);

    for (int t = 0; t < ntiles; t++) {
        int buf = t & 1;
        asm volatile("cp.async.wait_group 0;");
        __syncthreads();
        if (t + 1 < ntiles) issue(t + 1, (t + 1) & 1);

        uint32_t sAb = sA + buf * A_TILEH * 2;
        uint32_t sBb = sB + buf * B_TILEH * 2;
#pragma unroll
        for (int ks = 0; ks < 2; ks++) {
            uint32_t a[4][4];
#pragma unroll
            for (int i = 0; i < 4; i++)
                ldsm4(a[i], sAb + aBase[i] + ks * 32);
            uint32_t bf[2][4];
#pragma unroll
            for (int q = 0; q < 2; q++)
                ldsm4t(bf[q], sBb + bBase[q] + ks * 16 * BSTRH * 2);
#pragma unroll
            for (int i = 0; i < 4; i++)
#pragma unroll
                for (int j = 0; j < 4; j++) {
                    int q = j >> 1, o = (j & 1) * 2;
                    hmma16(c[i][j], a[i], bf[q][o], bf[q][o + 1]);
                }
        }
    }

#pragma unroll
    for (int i = 0; i < 4; i++) {
        int r0 = m0 + wm * 64 + i * 16 + g;
#pragma unroll
        for (int j = 0; j < 4; j++) {
            int col = n0 + wn * 32 + j * 8 + 2 * tig;
#pragma unroll
            for (int half = 0; half < 2; half++) {
                int m = r0 + half * 8;
                if (m >= M) continue;
                float v0 = c[i][j][2 * half + 0];
                float v1 = c[i][j][2 * half + 1];
                if (EPI == 1) {
                    const float* Rrow = (RMR == 0) ? R + (size_t)m * N
                                                   : arow<RMR>(R, m);
                    v0 += Rrow[col];
                    v1 += Rrow[col + 1];
                } else if (EPI == 2) {
                    v0 += bias[col];
                    v1 += bias[col + 1];
                    v0 = 0.5f * v0 * (1.f + erff(v0 * 0.70710678118654752f));
                    v1 = 0.5f * v1 * (1.f + erff(v1 * 0.70710678118654752f));
                } else if (EPI == 3) {
                    const float* Rrow = R + (size_t)m * N;
                    v0 += bias[col] + Rrow[col];
                    v1 += bias[col + 1] + Rrow[col + 1];
                }
                if (WH != 2)
                    *(float2*)(Cf + (size_t)m * N + col) = make_float2(v0, v1);
                if (WH >= 1)
                    *(__half2*)(Ch + (size_t)m * N + col) = __floats2half2_rn(v0, v1);
            }
        }
    }
}

// ---------------- fp16 tensor-core attention ---------------------------------
// K half [key][KSTRH]; V half transposed [d][VTS]; P half [16][PSTRH] per warp.
// m16n8k16: QK B-frag = half2 pairs along d in K rows; PV B-frag = half2 pairs
// along key in Vt rows. All smem half2 access patterns are 32-bank conflict-free.
#define KSTRH 72
#define PSTRH 72
#define VTSTRH_T 280
#define VTSTRH_S 136
#define TKPAD 272
#define SMEM_ATH ((TKPAD * KSTRH + DH * VTSTRH_T + 8 * 16 * PSTRH) * 2)

template <int NTILE, int VTS>
__device__ __forceinline__ void attn_kblock_h(
    const __half* __restrict__ Kh, const __half* __restrict__ Vth,
    __half* __restrict__ Pw,
    const uint32_t (&qa)[4][4], float (&oc)[8][4],
    float& sum0, float& sum1,
    int g, int tig, int keybase, int klimit)
{
    float sc[NTILE][4];
#pragma unroll
    for (int nt = 0; nt < NTILE; nt++) {
        sc[nt][0] = sc[nt][1] = sc[nt][2] = sc[nt][3] = 0.f;
        const __half* Kp = Kh + (keybase + nt * 8 + g) * KSTRH + 2 * tig;
#pragma unroll
        for (int ks = 0; ks < 4; ks++) {
            uint32_t b0 = *(const uint32_t*)(Kp + ks * 16);
            uint32_t b1 = *(const uint32_t*)(Kp + ks * 16 + 8);
            hmma16(sc[nt], qa[ks], b0, b1);
        }
    }
#pragma unroll
    for (int nt = 0; nt < NTILE; nt++) {
        int key = keybase + nt * 8 + 2 * tig;
        float e0 = (key     < klimit) ? __expf(sc[nt][0]) : 0.f;
        float e1 = (key + 1 < klimit) ? __expf(sc[nt][1]) : 0.f;
        float e2 = (key     < klimit) ? __expf(sc[nt][2]) : 0.f;
        float e3 = (key + 1 < klimit) ? __expf(sc[nt][3]) : 0.f;
        sum0 += e0 + e1;
        sum1 += e2 + e3;
        *(__half2*)(Pw + g * PSTRH + nt * 8 + 2 * tig)       = __floats2half2_rn(e0, e1);
        *(__half2*)(Pw + (g + 8) * PSTRH + nt * 8 + 2 * tig) = __floats2half2_rn(e2, e3);
    }
    __syncwarp();
    uint32_t pa[NTILE / 2][4];
#pragma unroll
    for (int kc = 0; kc < NTILE / 2; kc++) {
        int base = kc * 16 + 2 * tig;
        pa[kc][0] = *(const uint32_t*)(Pw + g * PSTRH + base);
        pa[kc][1] = *(const uint32_t*)(Pw + (g + 8) * PSTRH + base);
        pa[kc][2] = *(const uint32_t*)(Pw + g * PSTRH + base + 8);
        pa[kc][3] = *(const uint32_t*)(Pw + (g + 8) * PSTRH + base + 8);
    }
#pragma unroll
    for (int nt = 0; nt < 8; nt++) {
        const __half* Vp = Vth + (nt * 8 + g) * VTS + keybase + 2 * tig;
#pragma unroll
        for (int kc = 0; kc < NTILE / 2; kc++) {
            uint32_t b0 = *(const uint32_t*)(Vp + kc * 16);
            uint32_t b1 = *(const uint32_t*)(Vp + kc * 16 + 8);
            hmma16(oc[nt], pa[kc], b0, b1);
        }
    }
    __syncwarp();
}

// build 4 k16 Q fragments from two global half rows, scaled by 0.125
__device__ __forceinline__ void build_q(uint32_t (&qa)[4][4],
                                        const __half* Q0, const __half* Q1,
                                        int tig) {
    __half2 s = __floats2half2_rn(0.125f, 0.125f);
#pragma unroll
    for (int ks = 0; ks < 4; ks++) {
        __half2 v0 = __hmul2(*(const __half2*)(Q0 + ks * 16 + 2 * tig), s);
        __half2 v1 = __hmul2(*(const __half2*)(Q1 + ks * 16 + 2 * tig), s);
        __half2 v2 = __hmul2(*(const __half2*)(Q0 + ks * 16 + 2 * tig + 8), s);
        __half2 v3 = __hmul2(*(const __half2*)(Q1 + ks * 16 + 2 * tig + 8), s);
        qa[ks][0] = *(uint32_t*)&v0;
        qa[ks][1] = *(uint32_t*)&v1;
        qa[ks][2] = *(uint32_t*)&v2;
        qa[ks][3] = *(uint32_t*)&v3;
    }
}

// ---------------- temporal attention (fp16) ----------------------------------
__global__ void __launch_bounds__(256) attn_t_mma() {
    extern __shared__ __half smt[];
    __half* Kh  = smt;
    __half* Vth = Kh + TKPAD * KSTRH;
    __half* Ps  = Vth + DH * VTSTRH_T;

    int b = blockIdx.x >> 3, h = blockIdx.x & 7;
    const __half* base = g_QKV1h + (size_t)b * NT * 1536;
    const __half* Kg = base + 512 + h * 64;
    const __half* Vg = base + 1024 + h * 64;

    for (int i = threadIdx.x; i < TKPAD * 8; i += 256) {
        int t = i >> 3, c8 = (i & 7) * 8;
        uint4 kv = make_uint4(0, 0, 0, 0), vv = make_uint4(0, 0, 0, 0);
        if (t < NT) {
            kv = *(const uint4*)(Kg + (size_t)t * 1536 + c8);
            vv = *(const uint4*)(Vg + (size_t)t * 1536 + c8);
        }
        *(uint4*)(Kh + t * KSTRH + c8) = kv;
        const __half* vh = (const __half*)&vv;
#pragma unroll
        for (int j = 0; j < 8; j++)
            Vth[(c8 + j) * VTSTRH_T + t] = vh[j];
    }
    __syncthreads();

    int lane = threadIdx.x & 31, warp = threadIdx.x >> 5;
    int g = lane >> 2, tig = lane & 3;
    __half* Pw = Ps + warp * 16 * PSTRH;

    for (int qt = warp; qt < 17; qt += 8) {
        int q0 = qt * 16;
        int r0 = min(q0 + g, NT - 1), r1 = min(q0 + g + 8, NT - 1);
        uint32_t qa[4][4];
        build_q(qa, base + (size_t)r0 * 1536 + h * 64,
                    base + (size_t)r1 * 1536 + h * 64, tig);

        float oc[8][4];
#pragma unroll
        for (int nt = 0; nt < 8; nt++)
            oc[nt][0] = oc[nt][1] = oc[nt][2] = oc[nt][3] = 0.f;
        float sum0 = 0.f, sum1 = 0.f;

#pragma unroll
        for (int kb = 0; kb < 4; kb++)
            attn_kblock_h<8, VTSTRH_T>(Kh, Vth, Pw, qa, oc, sum0, sum1,
                                       g, tig, kb * 64, NT);
        attn_kblock_h<2, VTSTRH_T>(Kh, Vth, Pw, qa, oc, sum0, sum1,
                                   g, tig, 256, NT);

        sum0 += __shfl_xor_sync(0xffffffffu, sum0, 1);
        sum0 += __shfl_xor_sync(0xffffffffu, sum0, 2);
        sum1 += __shfl_xor_sync(0xffffffffu, sum1, 1);
        sum1 += __shfl_xor_sync(0xffffffffu, sum1, 2);
        float inv0 = 1.f / sum0, inv1 = 1.f / sum1;

        int row0 = q0 + g, row1 = q0 + g + 8;
        if (row0 < NT) {
            __half* op = g_O1h + ((size_t)b * NT + row0) * 512 + h * 64;
#pragma unroll
            for (int nt = 0; nt < 8; nt++)
                *(__half2*)(op + nt * 8 + 2 * tig) =
                    __floats2half2_rn(oc[nt][0] * inv0, oc[nt][1] * inv0);
        }
        if (row1 < NT) {
            __half* op = g_O1h + ((size_t)b * NT + row1) * 512 + h * 64;
#pragma unroll
            for (int nt = 0; nt < 8; nt++)
                *(__half2*)(op + nt * 8 + 2 * tig) =
                    __floats2half2_rn(oc[nt][2] * inv1, oc[nt][3] * inv1);
        }
    }
}

// ---------------- fused spatial: tf32 E-projection + fp16 attention ----------
#define ETSTR 76
#define KVSTR 72
#define SF_F32 (128 * ETSTR + 2 * 72 * KVSTR)                        // floats
#define SF_F16 (KPROJ * KSTRH + DH * VTSTRH_S + 8 * 16 * PSTRH)      // halves
#define SMEM_SFH (SF_F32 * 4 + SF_F16 * 2)

__global__ void __launch_bounds__(256) attn_s_fused(const float* __restrict__ E) {
    extern __shared__ char smc[];
    float* ET   = (float*)smc;
    float* Ksrc = ET + 128 * ETSTR;
    float* Vsrc = Ksrc + 72 * KVSTR;
    __half* Kh  = (__half*)(smc + SF_F32 * 4);
    __half* Vth = Kh + KPROJ * KSTRH;
    __half* Ps  = Vth + DH * VTSTRH_S;

    int blk = blockIdx.x;
    int fb = blk >> 3, h = blk & 7;
    const __half* baseh = g_QKV2h + (size_t)fb * NS * 1536;

    for (int i = threadIdx.x; i < 128 * 11; i += 256) {
        int kk = i / 11, j = 65 + i % 11;
        ET[kk * ETSTR + j] = 0.f;
    }
    for (int i = threadIdx.x; i < 7 * KVSTR; i += 256) {
        Ksrc[65 * KVSTR + i] = 0.f;
        Vsrc[65 * KVSTR + i] = 0.f;
    }
    for (int i = threadIdx.x; i < NS * 128; i += 256) {
        int j = i >> 7, kk = i & 127;
        ET[kk * ETSTR + j] = E[i];
    }
    for (int i = threadIdx.x; i < NS * 16; i += 256) {
        int j = i >> 4, c4 = (i & 15) * 4;
        uint2 kh = *(const uint2*)(baseh + (size_t)j * 1536 + 512 + h * 64 + c4);
        uint2 vh = *(const uint2*)(baseh + (size_t)j * 1536 + 1024 + h * 64 + c4);
        float2 k0 = __half22float2(*(__half2*)&kh.x);
        float2 k1 = __half22float2(*(__half2*)&kh.y);
        float2 v0 = __half22float2(*(__half2*)&vh.x);
        float2 v1 = __half22float2(*(__half2*)&vh.y);
        *(float4*)(Ksrc + j * KVSTR + c4) = make_float4(k0.x, k0.y, k1.x, k1.y);
        *(float4*)(Vsrc + j * KVSTR + c4) = make_float4(v0.x, v0.y, v1.x, v1.y);
    }
    __syncthreads();

    int lane = threadIdx.x & 31, warp = threadIdx.x >> 5;
    int g = lane >> 2, tig = lane & 3;

    // phase 1: KE/VE = E^T (128x72) @ K/V (72x64) via tf32 mma -> half buffers
    {
        int m0w = warp * 16;
        float ck[8][4], cv[8][4];
#pragma unroll
        for (int nf = 0; nf < 8; nf++) {
            ck[nf][0] = ck[nf][1] = ck[nf][2] = ck[nf][3] = 0.f;
            cv[nf][0] = cv[nf][1] = cv[nf][2] = cv[nf][3] = 0.f;
        }
#pragma unroll
        for (int ks = 0; ks < 9; ks++) {
            int j0 = ks * 8;
            float a[4];
            a[0] = ET[(m0w + g) * ETSTR + j0 + tig];
            a[1] = ET[(m0w + g + 8) * ETSTR + j0 + tig];
            a[2] = ET[(m0w + g) * ETSTR + j0 + tig + 4];
            a[3] = ET[(m0w + g + 8) * ETSTR + j0 + tig + 4];
#pragma unroll
            for (int nf = 0; nf < 8; nf++) {
                const float* Kp = Ksrc + (j0 + tig) * KVSTR + nf * 8 + g;
                mma8(ck[nf], a, __float_as_uint(Kp[0]), __float_as_uint(Kp[4 * KVSTR]));
                const float* Vp = Vsrc + (j0 + tig) * KVSTR + nf * 8 + g;
                mma8(cv[nf], a, __float_as_uint(Vp[0]), __float_as_uint(Vp[4 * KVSTR]));
            }
        }
#pragma unroll
        for (int nf = 0; nf < 8; nf++) {
            int col = nf * 8 + 2 * tig;
            *(__half2*)(Kh + (m0w + g) * KSTRH + col)     = __floats2half2_rn(ck[nf][0], ck[nf][1]);
            *(__half2*)(Kh + (m0w + g + 8) * KSTRH + col) = __floats2half2_rn(ck[nf][2], ck[nf][3]);
            Vth[(col + 0) * VTSTRH_S + m0w + g]     = __float2half(cv[nf][0]);
            Vth[(col + 1) * VTSTRH_S + m0w + g]     = __float2half(cv[nf][1]);
            Vth[(col + 0) * VTSTRH_S + m0w + g + 8] = __float2half(cv[nf][2]);
            Vth[(col + 1) * VTSTRH_S + m0w + g + 8] = __float2half(cv[nf][3]);
        }
    }
    __syncthreads();

    // phase 2: fp16 attention over 128 projected keys
    __half* Pw = Ps + warp * 16 * PSTRH;
    for (int qt = warp; qt < 5; qt += 8) {
        int q0 = qt * 16;
        int r0 = min(q0 + g, NS - 1), r1 = min(q0 + g + 8, NS - 1);
        uint32_t qa[4][4];
        build_q(qa, baseh + (size_t)r0 * 1536 + h * 64,
                    baseh + (size_t)r1 * 1536 + h * 64, tig);

        float oc[8][4];
#pragma unroll
        for (int nt = 0; nt < 8; nt++)
            oc[nt][0] = oc[nt][1] = oc[nt][2] = oc[nt][3] = 0.f;
        float sum0 = 0.f, sum1 = 0.f;

        attn_kblock_h<8, VTSTRH_S>(Kh, Vth, Pw, qa, oc, sum0, sum1,
                                   g, tig, 0, KPROJ);
        attn_kblock_h<8, VTSTRH_S>(Kh, Vth, Pw, qa, oc, sum0, sum1,
                                   g, tig, 64, KPROJ);

        sum0 += __shfl_xor_sync(0xffffffffu, sum0, 1);
        sum0 += __shfl_xor_sync(0xffffffffu, sum0, 2);
        sum1 += __shfl_xor_sync(0xffffffffu, sum1, 1);
        sum1 += __shfl_xor_sync(0xffffffffu, sum1, 2);
        float inv0 = 1.f / sum0, inv1 = 1.f / sum1;

        int row0 = q0 + g, row1 = q0 + g + 8;
        if (row0 < NS) {
            __half* op = g_O2h + ((size_t)fb * NS + row0) * 512 + h * 64;
#pragma unroll
            for (int nt = 0; nt < 8; nt++)
                *(__half2*)(op + nt * 8 + 2 * tig) =
                    __floats2half2_rn(oc[nt][0] * inv0, oc[nt][1] * inv0);
        }
        if (row1 < NS) {
            __half* op = g_O2h + ((size_t)fb * NS + row1) * 512 + h * 64;
#pragma unroll
            for (int nt = 0; nt < 8; nt++)
                *(__half2*)(op + nt * 8 + 2 * tig) =
                    __floats2half2_rn(oc[nt][2] * inv1, oc[nt][3] * inv1);
        }
    }
}

// ---------------- launch -----------------------------------------------------
extern "C" void kernel_launch(void* const* d_in, const int* in_sizes, int n_in,
                              void* d_out, int out_size) {
    const float* x      = (const float*)d_in[0];
    const float* Wqkv_t = (const float*)d_in[1];
    const float* Wo_t   = (const float*)d_in[2];
    const float* Wqkv_s = (const float*)d_in[3];
    const float* Wo_s   = (const float*)d_in[4];
    const float* E      = (const float*)d_in[5];
    const float* W1     = (const float*)d_in[6];
    const float* b1     = (const float*)d_in[7];
    const float* W2     = (const float*)d_in[8];
    const float* b2     = (const float*)d_in[9];
    float* out = (float*)d_out;
    (void)in_sizes; (void)n_in; (void)out_size;

    float *Y1, *Y2;
    __half *QKV1h, *QKV2h, *xh, *O1h, *Y1h, *O2h, *Y2h, *Hh;
    __half *Whqt, *Whot, *Whqs, *Whos, *Wh1, *Wh2;
    cudaGetSymbolAddress((void**)&Y1, g_Y1);
    cudaGetSymbolAddress((void**)&Y2, g_Y2);
    cudaGetSymbolAddress((void**)&QKV1h, g_QKV1h);
    cudaGetSymbolAddress((void**)&QKV2h, g_QKV2h);
    cudaGetSymbolAddress((void**)&xh, g_xh);
    cudaGetSymbolAddress((void**)&O1h, g_O1h);
    cudaGetSymbolAddress((void**)&Y1h, g_Y1h);
    cudaGetSymbolAddress((void**)&O2h, g_O2h);
    cudaGetSymbolAddress((void**)&Y2h, g_Y2h);
    cudaGetSymbolAddress((void**)&Hh, g_Hh);
    cudaGetSymbolAddress((void**)&Whqt, g_Whqt);
    cudaGetSymbolAddress((void**)&Whot, g_Whot);
    cudaGetSymbolAddress((void**)&Whqs, g_Whqs);
    cudaGetSymbolAddress((void**)&Whos, g_Whos);
    cudaGetSymbolAddress((void**)&Wh1, g_Wh1);
    cudaGetSymbolAddress((void**)&Wh2, g_Wh2);

    cudaFuncSetAttribute(attn_t_mma, cudaFuncAttributeMaxDynamicSharedMemorySize, SMEM_ATH);
    cudaFuncSetAttribute(attn_s_fused, cudaFuncAttributeMaxDynamicSharedMemorySize, SMEM_SFH);

    // ---- fp16 conversions ----
    auto cvt = [&](const float* src, __half* dst, int n) {
        int n4 = n / 4;
        cvt_half<<<(n4 + 255) / 256, 256>>>(src, dst, n4);
    };
    cvt(x, xh, (1 + FRAMES * PATCHES) * DIMX);
    cvt(Wqkv_t, Whqt, DIMX * 3 * DIMX);
    cvt(Wo_t, Whot, DIMX * DIMX);
    cvt(Wqkv_s, Whqs, DIMX * 3 * DIMX);
    cvt(Wo_s, Whos, DIMX * DIMX);
    cvt(W1, Wh1, DIMX * DFF);
    cvt(W2, Wh2, DFF * DIMX);

    // ---- temporal stage ----
    hgemm<0,1,0,2><<<dim3(3 * DIMX / 128, (MT + 127) / 128), 256, HGEMM_SMEM>>>(
        xh, Whqt, nullptr, QKV1h, nullptr, nullptr, MT, 3 * DIMX, DIMX);
    attn_t_mma<<<PATCHES * HEADS, 256, SMEM_ATH>>>();
    hgemm<1,0,1,1><<<dim3(DIMX / 128, (MT + 127) / 128), 256, HGEMM_SMEM>>>(
        O1h, Whot, Y1, Y1h, nullptr, x, MT, DIMX, DIMX);

    // ---- spatial stage ----
    hgemm<0,2,0,2><<<dim3(3 * DIMX / 128, MS / 128), 256, HGEMM_SMEM>>>(
        Y1h, Whqs, nullptr, QKV2h, nullptr, nullptr, MS, 3 * DIMX, DIMX);
    attn_s_fused<<<FRAMES * HEADS, 256, SMEM_SFH>>>(E);
    hgemm<1,0,2,1><<<dim3(DIMX / 128, MS / 128), 256, HGEMM_SMEM>>>(
        O2h, Whos, Y2, Y2h, nullptr, Y1, MS, DIMX, DIMX);

    // ---- FFN ----
    hgemm<2,0,0,2><<<dim3(DFF / 128, MS / 128), 256, HGEMM_SMEM>>>(
        Y2h, Wh1, nullptr, Hh, b1, nullptr, MS, DFF, DIMX);
    hgemm<3,0,0,0><<<dim3(DIMX / 128, MS / 128), 256, HGEMM_SMEM>>>(
        Hh, Wh2, out, nullptr, b2, Y2, MS, DIMX, DFF);
}